// round 15
// baseline (speedup 1.0000x reference)
#include <cuda_runtime.h>
#include <cuda_bf16.h>
#include <cuda_fp16.h>
#include <cstdint>
#include <math.h>

// Problem constants
#define BDIM 64
#define TDIM 64
#define SDIM 128
#define HDIM 1024
#define EDIM 1024
#define VDIM 32000
#define G3H  3072          // 3*H
#define QGH  4096          // q(1024) | gh1(3072)

typedef __nv_bfloat16 bf16;

// ---------------- scratch (static device globals; no allocation) ----------------
__device__ bf16  g_kprojb[(size_t)BDIM * SDIM * HDIM];   // [B,S,H] bf16
__device__ bf16  g_encYb [(size_t)BDIM * SDIM * HDIM];
__device__ bf16  g_xsb   [(size_t)TDIM * BDIM * EDIM];   // [T*B, E]
__device__ bf16  g_Wihxb [G3H * HDIM];                   // Wih0[:, H:2H]
__device__ bf16  g_Wih0cb[G3H * HDIM];                   // Wih0[:, 0:H]
__device__ bf16  g_Wih1b [G3H * HDIM];
__device__ bf16  g_Whh0b [G3H * HDIM];
__device__ bf16  g_Wcatb [QGH * HDIM];                   // [Wq; Whh1]
__device__ bf16  g_Wkb   [HDIM * HDIM];
__device__ bf16  g_Woutb [(size_t)VDIM * HDIM];
__device__ bf16  g_ysb   [(size_t)TDIM * BDIM * HDIM];
__device__ float g_Xg    [(size_t)TDIM * BDIM * G3H];    // x-part of gi0 (+bih0)
__device__ float g_bcat  [QGH];
__device__ float g_h     [2 * BDIM * HDIM];              // fp32 hidden
__device__ bf16  g_hb    [2 * BDIM * HDIM];              // bf16 mirror (GEMM A input)
__device__ float g_qgh1  [BDIM * QGH];                   // per-row: q | gh1
__device__ float g_attn  [BDIM * SDIM];
__device__ bf16  g_ctxb  [BDIM * HDIM];
__device__ float g_gh0   [BDIM * G3H];

// ---------------- helpers ----------------
__device__ __forceinline__ float fast_tanh(float x) {
    float y; asm("tanh.approx.f32 %0, %1;" : "=f"(y) : "f"(x)); return y;
}
__device__ __forceinline__ float fast_sigmoid(float x) {
    return 1.0f / (1.0f + __expf(-x));
}
__device__ __forceinline__ float warpReduceSum(float v) {
    #pragma unroll
    for (int o = 16; o > 0; o >>= 1) v += __shfl_xor_sync(0xffffffffu, v, o);
    return v;
}
__device__ __forceinline__ float warpReduceMax(float v) {
    #pragma unroll
    for (int o = 16; o > 0; o >>= 1) v = fmaxf(v, __shfl_xor_sync(0xffffffffu, v, o));
    return v;
}

__device__ __forceinline__ void mma16816(float* d, const unsigned* a, const unsigned* b) {
    asm volatile(
        "mma.sync.aligned.m16n8k16.row.col.f32.bf16.bf16.f32 "
        "{%0,%1,%2,%3},{%4,%5,%6,%7},{%8,%9},{%0,%1,%2,%3};"
        : "+f"(d[0]), "+f"(d[1]), "+f"(d[2]), "+f"(d[3])
        : "r"(a[0]), "r"(a[1]), "r"(a[2]), "r"(a[3]), "r"(b[0]), "r"(b[1]));
}

#define CPASYNC16(dst_u32, src_ptr) \
    asm volatile("cp.async.cg.shared.global [%0], [%1], 16;" :: "r"(dst_u32), "l"(src_ptr))
#define CPCOMMIT() asm volatile("cp.async.commit_group;")
#define CPWAIT(n)  asm volatile("cp.async.wait_group %0;" :: "n"(n))

#define LDSM_X4(r0, r1, r2, r3, addr) \
    asm volatile("ldmatrix.sync.aligned.m8n8.x4.shared.b16 {%0,%1,%2,%3}, [%4];" \
                 : "=r"(r0), "=r"(r1), "=r"(r2), "=r"(r3) : "r"(addr))

template <typename T> __device__ __forceinline__ T toOut(float v);
template <> __device__ __forceinline__ float toOut<float>(float v) { return v; }
template <> __device__ __forceinline__ bf16  toOut<bf16 >(float v) { return __float2bfloat16(v); }

// ============ big bf16 GEMM: depth-3 cp.async pipeline + ldmatrix ============
// Dynamic smem: As[3][128][40] | Bs[3][128][40]  (61,440 bytes)
#define TROW 40            // padded row (bf16 elems)
template <typename OutT, bool ROWMAP>
__global__ __launch_bounds__(256)
void mma_gemm(const bf16* __restrict__ A, const bf16* __restrict__ B,
              const float* __restrict__ bias, OutT* __restrict__ C,
              int M, int N, int K)
{
    constexpr int BM = 128, BN = 128, BK = 32;
    extern __shared__ __align__(16) bf16 smem[];
    bf16* Asp = smem;                        // 3 * 128 * 40
    bf16* Bsp = smem + 3 * BM * TROW;

    const int bm = blockIdx.y * BM;
    const int bn = blockIdx.x * BN;
    const int tid = threadIdx.x;
    const int lane = tid & 31;
    const int warp = tid >> 5;
    const int wm = (warp >> 2) * 64;
    const int wn = (warp & 3) * 32;

    float acc[4][4][4];
    #pragma unroll
    for (int i = 0; i < 4; i++)
        #pragma unroll
        for (int j = 0; j < 4; j++)
            #pragma unroll
            for (int x = 0; x < 4; x++) acc[i][j][x] = 0.0f;

    const int r  = lane >> 2;
    const int c2 = (lane & 3) * 2;
    const int lrowA = lane & 15;
    const int lkA   = (lane >> 4) * 8;
    const int lrowB = lane & 7;
    const int gB    = lane >> 3;

    auto load_stage = [&](int s, int k0) {
        bf16* As = Asp + (size_t)s * BM * TROW;
        bf16* Bs = Bsp + (size_t)s * BN * TROW;
        #pragma unroll
        for (int v = 0; v < 2; v++) {
            int idx = tid + v * 256;
            int row = idx >> 2;
            int c8  = (idx & 3) * 8;
            CPASYNC16((unsigned)__cvta_generic_to_shared(&As[row * TROW + c8]),
                      &A[(size_t)(bm + row) * K + k0 + c8]);
            CPASYNC16((unsigned)__cvta_generic_to_shared(&Bs[row * TROW + c8]),
                      &B[(size_t)(bn + row) * K + k0 + c8]);
        }
        CPCOMMIT();
    };

    const int NIT = K / BK;                  // always 32 here
    load_stage(0, 0);
    load_stage(1, BK);

    for (int it = 0; it < NIT; it++) {
        if (it + 2 < NIT) { load_stage((it + 2) % 3, (it + 2) * BK); CPWAIT(2); }
        else if (it + 1 < NIT) { CPWAIT(1); }
        else { CPWAIT(0); }
        __syncthreads();
        const int s = it % 3;
        bf16* As = Asp + (size_t)s * BM * TROW;
        bf16* Bs = Bsp + (size_t)s * BN * TROW;

        #pragma unroll
        for (int ks = 0; ks < 2; ks++) {
            unsigned a[4][4], b[4][2];
            #pragma unroll
            for (int i = 0; i < 4; i++) {
                unsigned ad = (unsigned)__cvta_generic_to_shared(
                    &As[(wm + i * 16 + lrowA) * TROW + ks * 16 + lkA]);
                LDSM_X4(a[i][0], a[i][1], a[i][2], a[i][3], ad);
            }
            #pragma unroll
            for (int jj = 0; jj < 2; jj++) {
                unsigned bd = (unsigned)__cvta_generic_to_shared(
                    &Bs[(wn + (jj * 2 + (gB >> 1)) * 8 + lrowB) * TROW + ks * 16 + (gB & 1) * 8]);
                unsigned r0, r1, r2, r3;
                LDSM_X4(r0, r1, r2, r3, bd);
                b[jj * 2][0] = r0; b[jj * 2][1] = r1;
                b[jj * 2 + 1][0] = r2; b[jj * 2 + 1][1] = r3;
            }
            #pragma unroll
            for (int i = 0; i < 4; i++)
                #pragma unroll
                for (int j = 0; j < 4; j++)
                    mma16816(acc[i][j], a[i], b[j]);
        }
        __syncthreads();
    }

    #pragma unroll
    for (int i = 0; i < 4; i++) {
        int grow0 = bm + wm + i * 16 + r;
        #pragma unroll
        for (int half = 0; half < 2; half++) {
            int g = grow0 + half * 8;
            size_t rowBase;
            if (ROWMAP) {
                int b_ = g & (BDIM - 1);
                int t_ = g >> 6;
                rowBase = (size_t)(b_ * TDIM + t_) * N;
            } else {
                rowBase = (size_t)g * N;
            }
            #pragma unroll
            for (int j = 0; j < 4; j++) {
                int col = bn + wn + j * 8 + c2;
                float b0 = bias ? bias[col]     : 0.0f;
                float b1 = bias ? bias[col + 1] : 0.0f;
                C[rowBase + col    ] = toOut<OutT>(acc[i][j][half * 2    ] + b0);
                C[rowBase + col + 1] = toOut<OutT>(acc[i][j][half * 2 + 1] + b1);
            }
        }
    }
}
#define MMA_SMEM 61440

// ============ 64x64 slab GEMM (cp.async double-buffered, R8 schedule) ============
__device__ __forceinline__ void slab64_body(
    const bf16* __restrict__ A, const bf16* __restrict__ W,
    const float* __restrict__ bias, float* __restrict__ C, int ldc, int bn)
{
    constexpr int PAD = 8;
    __shared__ __align__(16) bf16 sA[2][64][32 + PAD];
    __shared__ __align__(16) bf16 sW[2][64][32 + PAD];

    const int tid = threadIdx.x;
    const int lane = tid & 31;
    const int warp = tid >> 5;           // 2 M-warps x 4 N-warps
    const int wm = (warp >> 2) * 32;
    const int wn = (warp & 3) * 16;
    const int r  = lane >> 2;
    const int c2 = (lane & 3) * 2;

    float acc[2][2][4];
    #pragma unroll
    for (int i = 0; i < 2; i++)
        #pragma unroll
        for (int j = 0; j < 2; j++)
            #pragma unroll
            for (int x = 0; x < 4; x++) acc[i][j][x] = 0.0f;

    const int lrow = tid >> 2;            // 0..63
    const int lc8  = (tid & 3) * 8;       // 0,8,16,24

    auto load_stage = [&](int s, int k0) {
        CPASYNC16((unsigned)__cvta_generic_to_shared(&sA[s][lrow][lc8]),
                  &A[(size_t)lrow * HDIM + k0 + lc8]);
        CPASYNC16((unsigned)__cvta_generic_to_shared(&sW[s][lrow][lc8]),
                  &W[(size_t)(bn + lrow) * HDIM + k0 + lc8]);
        CPCOMMIT();
    };

    load_stage(0, 0);
    for (int it = 0; it < 32; it++) {
        if (it + 1 < 32) { load_stage((it + 1) & 1, (it + 1) * 32); CPWAIT(1); }
        else             { CPWAIT(0); }
        __syncthreads();
        const int s = it & 1;
        #pragma unroll
        for (int ks = 0; ks < 2; ks++) {
            unsigned a[2][4], b[2][2];
            #pragma unroll
            for (int i = 0; i < 2; i++) {
                int mr = wm + i * 16;
                a[i][0] = *reinterpret_cast<const unsigned*>(&sA[s][mr + r    ][ks * 16 + c2    ]);
                a[i][1] = *reinterpret_cast<const unsigned*>(&sA[s][mr + r + 8][ks * 16 + c2    ]);
                a[i][2] = *reinterpret_cast<const unsigned*>(&sA[s][mr + r    ][ks * 16 + c2 + 8]);
                a[i][3] = *reinterpret_cast<const unsigned*>(&sA[s][mr + r + 8][ks * 16 + c2 + 8]);
            }
            #pragma unroll
            for (int j = 0; j < 2; j++) {
                int nr = wn + j * 8 + r;
                b[j][0] = *reinterpret_cast<const unsigned*>(&sW[s][nr][ks * 16 + c2    ]);
                b[j][1] = *reinterpret_cast<const unsigned*>(&sW[s][nr][ks * 16 + c2 + 8]);
            }
            #pragma unroll
            for (int i = 0; i < 2; i++)
                #pragma unroll
                for (int j = 0; j < 2; j++)
                    mma16816(acc[i][j], a[i], b[j]);
        }
        __syncthreads();
    }

    #pragma unroll
    for (int i = 0; i < 2; i++)
        #pragma unroll
        for (int half = 0; half < 2; half++) {
            int row = wm + i * 16 + half * 8 + r;
            #pragma unroll
            for (int j = 0; j < 2; j++) {
                int col = bn + wn + j * 8 + c2;
                float v0 = acc[i][j][half * 2    ];
                float v1 = acc[i][j][half * 2 + 1];
                if (bias) { v0 += bias[col]; v1 += bias[col + 1]; }
                C[(size_t)row * ldc + col    ] = v0;
                C[(size_t)row * ldc + col + 1] = v1;
            }
        }
}

// step-start: 112 blocks. blk<64: qgh1 = h1 @ Wcat^T + bcat; else gh0 = h0 @ Whh0^T + bhh0
__global__ __launch_bounds__(256)
void step_start_kernel(const float* __restrict__ bhh0)
{
    const bf16* h0b = g_hb;
    const bf16* h1b = g_hb + BDIM * HDIM;
    if (blockIdx.x < 64)
        slab64_body(h1b, g_Wcatb, g_bcat, g_qgh1, QGH, blockIdx.x * 64);
    else
        slab64_body(h0b, g_Whh0b, bhh0, g_gh0, G3H, (blockIdx.x - 64) * 64);
}

// ---------------- attention scores: grid (32, 64), 128 thr; warp w -> s = blk*4+w ----
__global__ __launch_bounds__(128)
void attn_scores_kernel(const float* __restrict__ wv, const float* __restrict__ bv)
{
    const int lane = threadIdx.x & 31;
    const int warp = threadIdx.x >> 5;
    const int b = blockIdx.y;
    const int s = blockIdx.x * 4 + warp;

    const __nv_bfloat162* kp =
        reinterpret_cast<const __nv_bfloat162*>(&g_kprojb[((size_t)b * SDIM + s) * HDIM]);
    const float2* q2  = reinterpret_cast<const float2*>(&g_qgh1[(size_t)b * QGH]);
    const float2* wv2 = reinterpret_cast<const float2*>(wv);

    float sum = 0.0f;
    #pragma unroll 4
    for (int i = lane; i < HDIM / 2; i += 32) {
        __nv_bfloat162 k = kp[i];
        float2 q = q2[i];
        float2 w = wv2[i];
        __half2 hx = __floats2half2_rn(q.x + __low2float(k), q.y + __high2float(k));
        unsigned hin = *reinterpret_cast<unsigned*>(&hx);
        unsigned hout;
        asm("tanh.approx.f16x2 %0, %1;" : "=r"(hout) : "r"(hin));
        __half2 ht = *reinterpret_cast<__half2*>(&hout);
        float2 tv = __half22float2(ht);
        sum += tv.x * w.x + tv.y * w.y;
    }
    sum = warpReduceSum(sum);
    if (lane == 0) g_attn[b * SDIM + s] = sum + bv[0];
}

// ---------------- fused softmax + context: grid (4, B), 256 thr ----------------
__global__ __launch_bounds__(256)
void ctx_softmax_kernel()
{
    const int b = blockIdx.y;
    const int tid = threadIdx.x;
    __shared__ float sc[SDIM];
    __shared__ float red[8];

    float v = (tid < SDIM) ? g_attn[b * SDIM + tid] : -1e30f;
    float m = warpReduceMax(v);
    if ((tid & 31) == 0) red[tid >> 5] = m;
    __syncthreads();
    m = red[0];
    #pragma unroll
    for (int w = 1; w < 8; w++) m = fmaxf(m, red[w]);

    float e = (tid < SDIM) ? __expf(v - m) : 0.0f;
    float s = warpReduceSum(e);
    __syncthreads();
    if ((tid & 31) == 0) red[tid >> 5] = s;
    __syncthreads();
    float tot = red[0];
    #pragma unroll
    for (int w = 1; w < 8; w++) tot += red[w];

    if (tid < SDIM) sc[tid] = e / tot;
    __syncthreads();

    const int h = blockIdx.x * 256 + tid;
    const bf16* ey = &g_encYb[(size_t)b * SDIM * HDIM + h];
    float acc = 0.0f;
    #pragma unroll 8
    for (int s2 = 0; s2 < SDIM; s2++)
        acc = fmaf(sc[s2], __bfloat162float(ey[(size_t)s2 * HDIM]), acc);
    g_ctxb[b * HDIM + h] = __float2bfloat16(acc);
}

// ============ fused GRU: gi GEMM (16 cols x 3 gates per block, 64 blocks) + gate ============
__global__ __launch_bounds__(256)
void gru_fused_kernel(const bf16* __restrict__ A, const bf16* __restrict__ W,
                      const float* __restrict__ bias, const float* __restrict__ Xgt,
                      const float* __restrict__ GH, int ldgh,
                      float* __restrict__ h, bf16* __restrict__ hb,
                      bf16* __restrict__ ys)
{
    constexpr int PAD = 8;
    __shared__ __align__(16) bf16 sA[2][64][32 + PAD];
    __shared__ __align__(16) bf16 sW[2][3][16][32 + PAD];

    const int tid = threadIdx.x;
    const int lane = tid & 31;
    const int warp = tid >> 5;            // 4 M-warps x 2 N-warps
    const int wm  = (warp >> 1) * 16;
    const int wn8 = (warp & 1) * 8;
    const int r  = lane >> 2;
    const int c2 = (lane & 3) * 2;
    const int bn = blockIdx.x * 16;

    float acc[3][4];
    #pragma unroll
    for (int g = 0; g < 3; g++)
        #pragma unroll
        for (int x = 0; x < 4; x++) acc[g][x] = 0.0f;

    const int arow = tid >> 2, ac8 = (tid & 3) * 8;

    auto load_stage = [&](int s, int k0) {
        CPASYNC16((unsigned)__cvta_generic_to_shared(&sA[s][arow][ac8]),
                  &A[(size_t)arow * HDIM + k0 + ac8]);
        if (tid < 192) {                   // 3 gates x 16 rows x 4 chunks
            int gg  = tid >> 6;            // 0..2
            int rr2 = (tid >> 2) & 15;     // 0..15
            int c8  = (tid & 3) * 8;
            CPASYNC16((unsigned)__cvta_generic_to_shared(&sW[s][gg][rr2][c8]),
                      &W[(size_t)(gg * HDIM + bn + rr2) * HDIM + k0 + c8]);
        }
        CPCOMMIT();
    };

    load_stage(0, 0);
    for (int it = 0; it < 32; it++) {
        if (it + 1 < 32) { load_stage((it + 1) & 1, (it + 1) * 32); CPWAIT(1); }
        else             { CPWAIT(0); }
        __syncthreads();
        const int s = it & 1;
        #pragma unroll
        for (int ks = 0; ks < 2; ks++) {
            unsigned a[4];
            a[0] = *reinterpret_cast<const unsigned*>(&sA[s][wm + r    ][ks * 16 + c2    ]);
            a[1] = *reinterpret_cast<const unsigned*>(&sA[s][wm + r + 8][ks * 16 + c2    ]);
            a[2] = *reinterpret_cast<const unsigned*>(&sA[s][wm + r    ][ks * 16 + c2 + 8]);
            a[3] = *reinterpret_cast<const unsigned*>(&sA[s][wm + r + 8][ks * 16 + c2 + 8]);
            #pragma unroll
            for (int g = 0; g < 3; g++) {
                unsigned b[2];
                int nr = wn8 + r;
                b[0] = *reinterpret_cast<const unsigned*>(&sW[s][g][nr][ks * 16 + c2    ]);
                b[1] = *reinterpret_cast<const unsigned*>(&sW[s][g][nr][ks * 16 + c2 + 8]);
                mma16816(acc[g], a, b);
            }
        }
        __syncthreads();
    }

    // in-register GRU gate on the 4 (row,col) positions this thread owns
    #pragma unroll
    for (int half = 0; half < 2; half++) {
        int row = wm + half * 8 + r;            // b index (0..63)
        #pragma unroll
        for (int e = 0; e < 2; e++) {
            int col = bn + wn8 + c2 + e;        // j index (0..1023)
            float gr = acc[0][half * 2 + e];
            float gz = acc[1][half * 2 + e];
            float gn = acc[2][half * 2 + e];
            if (bias) {
                gr += bias[col];
                gz += bias[HDIM + col];
                gn += bias[2 * HDIM + col];
            }
            if (Xgt) {
                const float* xr = &Xgt[(size_t)row * G3H + col];
                gr += xr[0];
                gz += xr[HDIM];
                gn += xr[2 * HDIM];
            }
            const float* ghp = &GH[(size_t)row * ldgh + col];
            float rr = fast_sigmoid(gr + ghp[0]);
            float zz = fast_sigmoid(gz + ghp[HDIM]);
            float nn = fast_tanh(gn + rr * ghp[2 * HDIM]);
            int hi = row * HDIM + col;
            float hn = (1.0f - zz) * nn + zz * h[hi];
            h[hi]  = hn;
            bf16 hv = __float2bfloat16(hn);
            hb[hi] = hv;
            if (ys) ys[hi] = hv;
        }
    }
}

// ---------------- embedding gather -> bf16 (one block per (t,b) row) ----------------
__global__ void gather_kernel(const int* __restrict__ X, const float* __restrict__ table)
{
    const int tb = blockIdx.x;                 // t*64+b
    const int b = tb & (BDIM - 1);
    const int t = tb >> 6;
    const float4* src = reinterpret_cast<const float4*>(
        &table[(size_t)X[b * TDIM + t] * EDIM]);
    float4 f = src[threadIdx.x];
    bf16* dst = &g_xsb[(size_t)tb * EDIM + threadIdx.x * 4];
    dst[0] = __float2bfloat16(f.x);
    dst[1] = __float2bfloat16(f.y);
    dst[2] = __float2bfloat16(f.z);
    dst[3] = __float2bfloat16(f.w);
}

// ---------------- fused conversion: all fp32->bf16 jobs in ONE kernel ----------------
__device__ __forceinline__ void cvt4(const float* __restrict__ src, bf16* __restrict__ dst,
                                     size_t j)
{
    float4 f = reinterpret_cast<const float4*>(src)[j];
    __nv_bfloat162* d = reinterpret_cast<__nv_bfloat162*>(dst + j * 4);
    d[0] = __floats2bfloat162_rn(f.x, f.y);
    d[1] = __floats2bfloat162_rn(f.z, f.w);
}
// strided source: row-length cols from src rows of srcld with offset srcoff
__device__ __forceinline__ void cvt4_str(const float* __restrict__ src, int srcld, int srcoff,
                                         bf16* __restrict__ dst, size_t j)
{
    int cpr = HDIM / 4;
    int r = (int)(j / cpr);
    int c4 = (int)(j % cpr);
    float4 f = *reinterpret_cast<const float4*>(&src[(size_t)r * srcld + srcoff + c4 * 4]);
    __nv_bfloat162* d = reinterpret_cast<__nv_bfloat162*>(dst + (size_t)r * HDIM + c4 * 4);
    d[0] = __floats2bfloat162_rn(f.x, f.y);
    d[1] = __floats2bfloat162_rn(f.z, f.w);
}

#define N_ENCY4 ((size_t)BDIM * SDIM * HDIM / 4)   // 2,097,152
#define N_WK4   ((size_t)HDIM * HDIM / 4)          //   262,144
#define N_WOUT4 ((size_t)VDIM * HDIM / 4)          // 8,192,000
#define N_W3H4  ((size_t)G3H * HDIM / 4)           //   786,432
#define N_WCAT4 ((size_t)QGH * HDIM / 4)           // 1,048,576
#define N_CONV_TOTAL (N_ENCY4 + N_WK4 + N_WOUT4 + 4 * N_W3H4 + N_WCAT4)  // 14,745,600

__global__ __launch_bounds__(256)
void convert_all_kernel(const float* __restrict__ encY, const float* __restrict__ Wk,
                        const float* __restrict__ Wout, const float* __restrict__ Whh0,
                        const float* __restrict__ Wih1, const float* __restrict__ Wih0,
                        const float* __restrict__ Wq,   const float* __restrict__ Whh1)
{
    size_t i = (size_t)blockIdx.x * 256 + threadIdx.x;
    size_t base = 0;
    if (i < base + N_ENCY4) { cvt4(encY, g_encYb, i - base); return; }
    base += N_ENCY4;
    if (i < base + N_WK4)   { cvt4(Wk, g_Wkb, i - base); return; }
    base += N_WK4;
    if (i < base + N_WOUT4) { cvt4(Wout, g_Woutb, i - base); return; }
    base += N_WOUT4;
    if (i < base + N_W3H4)  { cvt4(Whh0, g_Whh0b, i - base); return; }
    base += N_W3H4;
    if (i < base + N_W3H4)  { cvt4(Wih1, g_Wih1b, i - base); return; }
    base += N_W3H4;
    if (i < base + N_W3H4)  { cvt4_str(Wih0, 2 * HDIM, HDIM, g_Wihxb, i - base); return; }
    base += N_W3H4;
    if (i < base + N_W3H4)  { cvt4_str(Wih0, 2 * HDIM, 0, g_Wih0cb, i - base); return; }
    base += N_W3H4;
    {
        size_t j = i - base;               // Wcat: [Wq; Whh1]
        size_t e = j * 4;
        int rr = (int)(e / HDIM);
        int c  = (int)(e % HDIM);
        const float* s = (rr < HDIM) ? &Wq[(size_t)rr * HDIM + c]
                                     : &Whh1[(size_t)(rr - HDIM) * HDIM + c];
        float4 f = *reinterpret_cast<const float4*>(s);
        __nv_bfloat162* d = reinterpret_cast<__nv_bfloat162*>(&g_Wcatb[e]);
        d[0] = __floats2bfloat162_rn(f.x, f.y);
        d[1] = __floats2bfloat162_rn(f.z, f.w);
    }
}

__global__ void bcat_kernel(const float* __restrict__ bq, const float* __restrict__ bhh1)
{
    int i = blockIdx.x * blockDim.x + threadIdx.x;
    if (i >= QGH) return;
    g_bcat[i] = (i < HDIM) ? bq[i] : bhh1[i - HDIM];
}

// ---------------- init hidden: fp32 copy + bf16 mirror ----------------
__global__ void hinit_kernel(const float* __restrict__ h0in)
{
    int i = blockIdx.x * blockDim.x + threadIdx.x;
    if (i >= 2 * BDIM * HDIM) return;
    float v = h0in[i];
    g_h[i]  = v;
    g_hb[i] = __float2bfloat16(v);
}

// ---------------- in-place log-softmax over V (3-pass, champion version) ----------------
__global__ __launch_bounds__(256)
void logsoftmax_kernel(float* __restrict__ out)
{
    float4* p4 = reinterpret_cast<float4*>(out + (size_t)blockIdx.x * VDIM);
    const int n4 = VDIM / 4;
    const int tid = threadIdx.x;

    float m = -1e30f;
    for (int v = tid; v < n4; v += 256) {
        float4 f = p4[v];
        m = fmaxf(m, fmaxf(fmaxf(f.x, f.y), fmaxf(f.z, f.w)));
    }
    m = warpReduceMax(m);
    __shared__ float shm[8];
    if ((tid & 31) == 0) shm[tid >> 5] = m;
    __syncthreads();
    m = shm[0];
    #pragma unroll
    for (int w = 1; w < 8; w++) m = fmaxf(m, shm[w]);

    float s = 0.0f;
    for (int v = tid; v < n4; v += 256) {
        float4 f = p4[v];
        s += __expf(f.x - m) + __expf(f.y - m) + __expf(f.z - m) + __expf(f.w - m);
    }
    s = warpReduceSum(s);
    __shared__ float shs[8];
    if ((tid & 31) == 0) shs[tid >> 5] = s;
    __syncthreads();
    s = shs[0];
    #pragma unroll
    for (int w = 1; w < 8; w++) s += shs[w];

    const float lse = m + logf(s);
    for (int v = tid; v < n4; v += 256) {
        float4 f = p4[v];
        f.x -= lse; f.y -= lse; f.z -= lse; f.w -= lse;
        p4[v] = f;
    }
}

// ---------------- launcher ----------------
extern "C" void kernel_launch(void* const* d_in, const int* in_sizes, int n_in,
                              void* d_out, int out_size)
{
    (void)in_sizes; (void)n_in; (void)out_size;

    const int*   X     = (const int*)d_in[0];
    const float* encY  = (const float*)d_in[1];
    const float* h0in  = (const float*)d_in[2];
    const float* table = (const float*)d_in[3];
    const float* Wq    = (const float*)d_in[4];
    const float* bq    = (const float*)d_in[5];
    const float* Wk    = (const float*)d_in[6];
    const float* bk    = (const float*)d_in[7];
    const float* wv    = (const float*)d_in[8];
    const float* bv    = (const float*)d_in[9];
    const float* Wih0  = (const float*)d_in[10];
    const float* Whh0  = (const float*)d_in[11];
    const float* bih0  = (const float*)d_in[12];
    const float* bhh0  = (const float*)d_in[13];
    const float* Wih1  = (const float*)d_in[14];
    const float* Whh1  = (const float*)d_in[15];
    const float* bih1  = (const float*)d_in[16];
    const float* bhh1  = (const float*)d_in[17];
    const float* Wout  = (const float*)d_in[18];
    const float* bout  = (const float*)d_in[19];
    float* out = (float*)d_out;

    bf16 *kprojb, *encYb, *xsb, *Wihxb, *Wih0cb, *Wih1b, *Woutb, *Wkb, *ysb, *hb, *ctxb;
    float *Xg, *h, *gh0, *qgh1;
    cudaGetSymbolAddress((void**)&kprojb, g_kprojb);
    cudaGetSymbolAddress((void**)&encYb,  g_encYb);
    cudaGetSymbolAddress((void**)&xsb,    g_xsb);
    cudaGetSymbolAddress((void**)&Wihxb,  g_Wihxb);
    cudaGetSymbolAddress((void**)&Wih0cb, g_Wih0cb);
    cudaGetSymbolAddress((void**)&Wih1b,  g_Wih1b);
    cudaGetSymbolAddress((void**)&Woutb,  g_Woutb);
    cudaGetSymbolAddress((void**)&Wkb,    g_Wkb);
    cudaGetSymbolAddress((void**)&ysb,    g_ysb);
    cudaGetSymbolAddress((void**)&hb,     g_hb);
    cudaGetSymbolAddress((void**)&ctxb,   g_ctxb);
    cudaGetSymbolAddress((void**)&Xg,     g_Xg);
    cudaGetSymbolAddress((void**)&h,      g_h);
    cudaGetSymbolAddress((void**)&gh0,    g_gh0);
    cudaGetSymbolAddress((void**)&qgh1,   g_qgh1);

    // raise dynamic smem limit for the depth-3 GEMM (idempotent host calls)
    cudaFuncSetAttribute(mma_gemm<bf16,  false>,
                         cudaFuncAttributeMaxDynamicSharedMemorySize, MMA_SMEM);
    cudaFuncSetAttribute(mma_gemm<float, false>,
                         cudaFuncAttributeMaxDynamicSharedMemorySize, MMA_SMEM);
    cudaFuncSetAttribute(mma_gemm<float, true>,
                         cudaFuncAttributeMaxDynamicSharedMemorySize, MMA_SMEM);

    // ---- prologue: gather + ONE fused conversion + small init ----
    gather_kernel<<<TDIM * BDIM, 256>>>(X, table);
    convert_all_kernel<<<(unsigned)(N_CONV_TOTAL / 256), 256>>>(
        encY, Wk, Wout, Whh0, Wih1, Wih0, Wq, Whh1);
    bcat_kernel<<<(QGH + 255) / 256, 256>>>(bq, bhh1);
    hinit_kernel<<<(2 * BDIM * HDIM + 255) / 256, 256>>>(h0in);

    // kproj (bf16 out), Xg (fp32, bih0 folded)
    mma_gemm<bf16, false><<<dim3(HDIM / 128, (BDIM * SDIM) / 128), 256, MMA_SMEM>>>(
        encYb, Wkb, bk, kprojb, BDIM * SDIM, HDIM, HDIM);
    mma_gemm<float, false><<<dim3(G3H / 128, (TDIM * BDIM) / 128), 256, MMA_SMEM>>>(
        xsb, Wihxb, bih0, Xg, TDIM * BDIM, G3H, HDIM);

    bf16* h0b = hb;
    bf16* h1b = hb + BDIM * HDIM;
    float* h0p = h;
    float* h1p = h + BDIM * HDIM;

    // ---- recurrent scan: 5 launches per step ----
    for (int t = 0; t < TDIM; t++) {
        step_start_kernel<<<112, 256>>>(bhh0);
        attn_scores_kernel<<<dim3(SDIM / 4, BDIM), 128>>>(wv, bv);
        ctx_softmax_kernel<<<dim3(4, BDIM), 256>>>();
        gru_fused_kernel<<<64, 256>>>(ctxb, Wih0cb, nullptr,
                                      Xg + (size_t)t * BDIM * G3H,
                                      gh0, G3H, h0p, h0b, nullptr);
        gru_fused_kernel<<<64, 256>>>(h0b, Wih1b, bih1, nullptr,
                                      qgh1 + HDIM, QGH, h1p, h1b,
                                      ysb + (size_t)t * BDIM * HDIM);
    }

    // ---- logits (tensor core, ROWMAP into [B,T,V]) + log-softmax ----
    mma_gemm<float, true><<<dim3(VDIM / 128, (TDIM * BDIM) / 128), 256, MMA_SMEM>>>(
        ysb, Woutb, bout, out, TDIM * BDIM, VDIM, HDIM);
    logsoftmax_kernel<<<BDIM * TDIM, 256>>>(out);
}

// round 16
// speedup vs baseline: 1.0154x; 1.0154x over previous
#include <cuda_runtime.h>
#include <cuda_bf16.h>
#include <cuda_fp16.h>
#include <cstdint>
#include <math.h>

// Problem constants
#define BDIM 64
#define TDIM 64
#define SDIM 128
#define HDIM 1024
#define EDIM 1024
#define VDIM 32000
#define G3H  3072          // 3*H
#define QGH  4096          // q(1024) | gh1(3072)

typedef __nv_bfloat16 bf16;

// ---------------- scratch (static device globals; no allocation) ----------------
__device__ bf16  g_kprojb[(size_t)BDIM * SDIM * HDIM];   // [B,S,H] bf16
__device__ bf16  g_encYb [(size_t)BDIM * SDIM * HDIM];
__device__ bf16  g_xsb   [(size_t)TDIM * BDIM * EDIM];   // [T*B, E]
__device__ bf16  g_Wihxb [G3H * HDIM];                   // Wih0[:, H:2H]
__device__ bf16  g_Wih0cb[G3H * HDIM];                   // Wih0[:, 0:H]
__device__ bf16  g_Wih1b [G3H * HDIM];
__device__ bf16  g_Whh0b [G3H * HDIM];
__device__ bf16  g_Wcatb [QGH * HDIM];                   // [Wq; Whh1]
__device__ bf16  g_Wkb   [HDIM * HDIM];
__device__ bf16  g_Woutb [(size_t)VDIM * HDIM];
__device__ bf16  g_ysb   [(size_t)TDIM * BDIM * HDIM];
__device__ float g_Xg    [(size_t)TDIM * BDIM * G3H];    // x-part of gi0 (+bih0)
__device__ float g_bcat  [QGH];
__device__ float g_h     [2 * BDIM * HDIM];              // fp32 hidden
__device__ bf16  g_hb    [2 * BDIM * HDIM];              // bf16 mirror (GEMM A input)
__device__ float g_qgh1  [BDIM * QGH];                   // per-row: q | gh1
__device__ float g_attn  [BDIM * SDIM];
__device__ bf16  g_ctxb  [BDIM * HDIM];
__device__ float g_gh0   [BDIM * G3H];

// ---------------- helpers ----------------
__device__ __forceinline__ float fast_tanh(float x) {
    float y; asm("tanh.approx.f32 %0, %1;" : "=f"(y) : "f"(x)); return y;
}
__device__ __forceinline__ float fast_sigmoid(float x) {
    return 1.0f / (1.0f + __expf(-x));
}
__device__ __forceinline__ float warpReduceSum(float v) {
    #pragma unroll
    for (int o = 16; o > 0; o >>= 1) v += __shfl_xor_sync(0xffffffffu, v, o);
    return v;
}
__device__ __forceinline__ float warpReduceMax(float v) {
    #pragma unroll
    for (int o = 16; o > 0; o >>= 1) v = fmaxf(v, __shfl_xor_sync(0xffffffffu, v, o));
    return v;
}

__device__ __forceinline__ void mma16816(float* d, const unsigned* a, const unsigned* b) {
    asm volatile(
        "mma.sync.aligned.m16n8k16.row.col.f32.bf16.bf16.f32 "
        "{%0,%1,%2,%3},{%4,%5,%6,%7},{%8,%9},{%0,%1,%2,%3};"
        : "+f"(d[0]), "+f"(d[1]), "+f"(d[2]), "+f"(d[3])
        : "r"(a[0]), "r"(a[1]), "r"(a[2]), "r"(a[3]), "r"(b[0]), "r"(b[1]));
}

#define CPASYNC16(dst_u32, src_ptr) \
    asm volatile("cp.async.cg.shared.global [%0], [%1], 16;" :: "r"(dst_u32), "l"(src_ptr))
#define CPCOMMIT() asm volatile("cp.async.commit_group;")
#define CPWAIT(n)  asm volatile("cp.async.wait_group %0;" :: "n"(n))

#define LDSM_X4(r0, r1, r2, r3, addr) \
    asm volatile("ldmatrix.sync.aligned.m8n8.x4.shared.b16 {%0,%1,%2,%3}, [%4];" \
                 : "=r"(r0), "=r"(r1), "=r"(r2), "=r"(r3) : "r"(addr))

template <typename T> __device__ __forceinline__ T toOut(float v);
template <> __device__ __forceinline__ float toOut<float>(float v) { return v; }
template <> __device__ __forceinline__ bf16  toOut<bf16 >(float v) { return __float2bfloat16(v); }

// ============ big bf16 tensor-core GEMM (R14 champion: 2-stage cp.async + ldmatrix) ============
template <typename OutT, bool ROWMAP>
__global__ __launch_bounds__(256)
void mma_gemm(const bf16* __restrict__ A, const bf16* __restrict__ B,
              const float* __restrict__ bias, OutT* __restrict__ C,
              int M, int N, int K)
{
    constexpr int BM = 128, BN = 128, BK = 32, PAD = 8;
    __shared__ __align__(16) bf16 As[2][BM][BK + PAD];
    __shared__ __align__(16) bf16 Bs[2][BN][BK + PAD];

    const int bm = blockIdx.y * BM;
    const int bn = blockIdx.x * BN;
    const int tid = threadIdx.x;
    const int lane = tid & 31;
    const int warp = tid >> 5;
    const int wm = (warp >> 2) * 64;
    const int wn = (warp & 3) * 32;

    float acc[4][4][4];
    #pragma unroll
    for (int i = 0; i < 4; i++)
        #pragma unroll
        for (int j = 0; j < 4; j++)
            #pragma unroll
            for (int x = 0; x < 4; x++) acc[i][j][x] = 0.0f;

    const int r  = lane >> 2;
    const int c2 = (lane & 3) * 2;
    const int lrowA = lane & 15;
    const int lkA   = (lane >> 4) * 8;
    const int lrowB = lane & 7;
    const int gB    = lane >> 3;

    auto load_stage = [&](int s, int k0) {
        #pragma unroll
        for (int v = 0; v < 2; v++) {
            int idx = tid + v * 256;
            int row = idx >> 2;
            int c8  = (idx & 3) * 8;
            CPASYNC16((unsigned)__cvta_generic_to_shared(&As[s][row][c8]),
                      &A[(size_t)(bm + row) * K + k0 + c8]);
            CPASYNC16((unsigned)__cvta_generic_to_shared(&Bs[s][row][c8]),
                      &B[(size_t)(bn + row) * K + k0 + c8]);
        }
        CPCOMMIT();
    };

    const int NIT = K / BK;
    load_stage(0, 0);

    for (int it = 0; it < NIT; it++) {
        if (it + 1 < NIT) load_stage((it + 1) & 1, (it + 1) * BK);
        if (it + 1 < NIT) { CPWAIT(1); } else { CPWAIT(0); }
        __syncthreads();
        const int s = it & 1;

        #pragma unroll
        for (int ks = 0; ks < 2; ks++) {
            unsigned a[4][4], b[4][2];
            #pragma unroll
            for (int i = 0; i < 4; i++) {
                unsigned ad = (unsigned)__cvta_generic_to_shared(
                    &As[s][wm + i * 16 + lrowA][ks * 16 + lkA]);
                LDSM_X4(a[i][0], a[i][1], a[i][2], a[i][3], ad);
            }
            #pragma unroll
            for (int jj = 0; jj < 2; jj++) {
                unsigned bd = (unsigned)__cvta_generic_to_shared(
                    &Bs[s][wn + (jj * 2 + (gB >> 1)) * 8 + lrowB][ks * 16 + (gB & 1) * 8]);
                unsigned r0, r1, r2, r3;
                LDSM_X4(r0, r1, r2, r3, bd);
                b[jj * 2][0] = r0; b[jj * 2][1] = r1;
                b[jj * 2 + 1][0] = r2; b[jj * 2 + 1][1] = r3;
            }
            #pragma unroll
            for (int i = 0; i < 4; i++)
                #pragma unroll
                for (int j = 0; j < 4; j++)
                    mma16816(acc[i][j], a[i], b[j]);
        }
        __syncthreads();
    }

    #pragma unroll
    for (int i = 0; i < 4; i++) {
        int grow0 = bm + wm + i * 16 + r;
        #pragma unroll
        for (int half = 0; half < 2; half++) {
            int g = grow0 + half * 8;
            size_t rowBase;
            if (ROWMAP) {
                int b_ = g & (BDIM - 1);
                int t_ = g >> 6;
                rowBase = (size_t)(b_ * TDIM + t_) * N;
            } else {
                rowBase = (size_t)g * N;
            }
            #pragma unroll
            for (int j = 0; j < 4; j++) {
                int col = bn + wn + j * 8 + c2;
                float b0 = bias ? bias[col]     : 0.0f;
                float b1 = bias ? bias[col + 1] : 0.0f;
                C[rowBase + col    ] = toOut<OutT>(acc[i][j][half * 2    ] + b0);
                C[rowBase + col + 1] = toOut<OutT>(acc[i][j][half * 2 + 1] + b1);
            }
        }
    }
}

// ============ 64x64 slab GEMM: depth-3 cp.async pipeline ============
__device__ __forceinline__ void slab64_body(
    const bf16* __restrict__ A, const bf16* __restrict__ W,
    const float* __restrict__ bias, float* __restrict__ C, int ldc, int bn)
{
    constexpr int PAD = 8;
    __shared__ __align__(16) bf16 sA[3][64][32 + PAD];
    __shared__ __align__(16) bf16 sW[3][64][32 + PAD];

    const int tid = threadIdx.x;
    const int lane = tid & 31;
    const int warp = tid >> 5;           // 2 M-warps x 4 N-warps
    const int wm = (warp >> 2) * 32;
    const int wn = (warp & 3) * 16;
    const int r  = lane >> 2;
    const int c2 = (lane & 3) * 2;

    float acc[2][2][4];
    #pragma unroll
    for (int i = 0; i < 2; i++)
        #pragma unroll
        for (int j = 0; j < 2; j++)
            #pragma unroll
            for (int x = 0; x < 4; x++) acc[i][j][x] = 0.0f;

    const int lrow = tid >> 2;            // 0..63
    const int lc8  = (tid & 3) * 8;       // 0,8,16,24

    auto load_stage = [&](int s, int k0) {
        CPASYNC16((unsigned)__cvta_generic_to_shared(&sA[s][lrow][lc8]),
                  &A[(size_t)lrow * HDIM + k0 + lc8]);
        CPASYNC16((unsigned)__cvta_generic_to_shared(&sW[s][lrow][lc8]),
                  &W[(size_t)(bn + lrow) * HDIM + k0 + lc8]);
        CPCOMMIT();
    };

    load_stage(0, 0);
    load_stage(1, 32);
    for (int it = 0; it < 32; it++) {
        if (it + 2 < 32)      { load_stage((it + 2) % 3, (it + 2) * 32); CPWAIT(2); }
        else if (it + 1 < 32) { CPWAIT(1); }
        else                  { CPWAIT(0); }
        __syncthreads();
        const int s = it % 3;
        #pragma unroll
        for (int ks = 0; ks < 2; ks++) {
            unsigned a[2][4], b[2][2];
            #pragma unroll
            for (int i = 0; i < 2; i++) {
                int mr = wm + i * 16;
                a[i][0] = *reinterpret_cast<const unsigned*>(&sA[s][mr + r    ][ks * 16 + c2    ]);
                a[i][1] = *reinterpret_cast<const unsigned*>(&sA[s][mr + r + 8][ks * 16 + c2    ]);
                a[i][2] = *reinterpret_cast<const unsigned*>(&sA[s][mr + r    ][ks * 16 + c2 + 8]);
                a[i][3] = *reinterpret_cast<const unsigned*>(&sA[s][mr + r + 8][ks * 16 + c2 + 8]);
            }
            #pragma unroll
            for (int j = 0; j < 2; j++) {
                int nr = wn + j * 8 + r;
                b[j][0] = *reinterpret_cast<const unsigned*>(&sW[s][nr][ks * 16 + c2    ]);
                b[j][1] = *reinterpret_cast<const unsigned*>(&sW[s][nr][ks * 16 + c2 + 8]);
            }
            #pragma unroll
            for (int i = 0; i < 2; i++)
                #pragma unroll
                for (int j = 0; j < 2; j++)
                    mma16816(acc[i][j], a[i], b[j]);
        }
        __syncthreads();
    }

    #pragma unroll
    for (int i = 0; i < 2; i++)
        #pragma unroll
        for (int half = 0; half < 2; half++) {
            int row = wm + i * 16 + half * 8 + r;
            #pragma unroll
            for (int j = 0; j < 2; j++) {
                int col = bn + wn + j * 8 + c2;
                float v0 = acc[i][j][half * 2    ];
                float v1 = acc[i][j][half * 2 + 1];
                if (bias) { v0 += bias[col]; v1 += bias[col + 1]; }
                C[(size_t)row * ldc + col    ] = v0;
                C[(size_t)row * ldc + col + 1] = v1;
            }
        }
}

// step-start: 112 blocks. blk<64: qgh1 = h1 @ Wcat^T + bcat; else gh0 = h0 @ Whh0^T + bhh0
__global__ __launch_bounds__(256)
void step_start_kernel(const float* __restrict__ bhh0)
{
    const bf16* h0b = g_hb;
    const bf16* h1b = g_hb + BDIM * HDIM;
    if (blockIdx.x < 64)
        slab64_body(h1b, g_Wcatb, g_bcat, g_qgh1, QGH, blockIdx.x * 64);
    else
        slab64_body(h0b, g_Whh0b, bhh0, g_gh0, G3H, (blockIdx.x - 64) * 64);
}

// ---------------- attention scores: grid (32, 64), 128 thr; warp w -> s = blk*4+w ----
__global__ __launch_bounds__(128)
void attn_scores_kernel(const float* __restrict__ wv, const float* __restrict__ bv)
{
    const int lane = threadIdx.x & 31;
    const int warp = threadIdx.x >> 5;
    const int b = blockIdx.y;
    const int s = blockIdx.x * 4 + warp;

    const __nv_bfloat162* kp =
        reinterpret_cast<const __nv_bfloat162*>(&g_kprojb[((size_t)b * SDIM + s) * HDIM]);
    const float2* q2  = reinterpret_cast<const float2*>(&g_qgh1[(size_t)b * QGH]);
    const float2* wv2 = reinterpret_cast<const float2*>(wv);

    float sum = 0.0f;
    #pragma unroll 4
    for (int i = lane; i < HDIM / 2; i += 32) {
        __nv_bfloat162 k = kp[i];
        float2 q = q2[i];
        float2 w = wv2[i];
        __half2 hx = __floats2half2_rn(q.x + __low2float(k), q.y + __high2float(k));
        unsigned hin = *reinterpret_cast<unsigned*>(&hx);
        unsigned hout;
        asm("tanh.approx.f16x2 %0, %1;" : "=r"(hout) : "r"(hin));
        __half2 ht = *reinterpret_cast<__half2*>(&hout);
        float2 tv = __half22float2(ht);
        sum += tv.x * w.x + tv.y * w.y;
    }
    sum = warpReduceSum(sum);
    if (lane == 0) g_attn[b * SDIM + s] = sum + bv[0];
}

// ---------------- fused softmax + context: grid (4, B), 256 thr ----------------
__global__ __launch_bounds__(256)
void ctx_softmax_kernel()
{
    const int b = blockIdx.y;
    const int tid = threadIdx.x;
    __shared__ float sc[SDIM];
    __shared__ float red[8];

    float v = (tid < SDIM) ? g_attn[b * SDIM + tid] : -1e30f;
    float m = warpReduceMax(v);
    if ((tid & 31) == 0) red[tid >> 5] = m;
    __syncthreads();
    m = red[0];
    #pragma unroll
    for (int w = 1; w < 8; w++) m = fmaxf(m, red[w]);

    float e = (tid < SDIM) ? __expf(v - m) : 0.0f;
    float s = warpReduceSum(e);
    __syncthreads();
    if ((tid & 31) == 0) red[tid >> 5] = s;
    __syncthreads();
    float tot = red[0];
    #pragma unroll
    for (int w = 1; w < 8; w++) tot += red[w];

    if (tid < SDIM) sc[tid] = e / tot;
    __syncthreads();

    const int h = blockIdx.x * 256 + tid;
    const bf16* ey = &g_encYb[(size_t)b * SDIM * HDIM + h];
    float acc = 0.0f;
    #pragma unroll 8
    for (int s2 = 0; s2 < SDIM; s2++)
        acc = fmaf(sc[s2], __bfloat162float(ey[(size_t)s2 * HDIM]), acc);
    g_ctxb[b * HDIM + h] = __float2bfloat16(acc);
}

// ============ fused GRU: gi GEMM (16 cols x 3 gates, 64 blocks, depth-3) + gate ============
__global__ __launch_bounds__(256)
void gru_fused_kernel(const bf16* __restrict__ A, const bf16* __restrict__ W,
                      const float* __restrict__ bias, const float* __restrict__ Xgt,
                      const float* __restrict__ GH, int ldgh,
                      float* __restrict__ h, bf16* __restrict__ hb,
                      bf16* __restrict__ ys)
{
    constexpr int PAD = 8;
    __shared__ __align__(16) bf16 sA[3][64][32 + PAD];
    __shared__ __align__(16) bf16 sW[3][3][16][32 + PAD];

    const int tid = threadIdx.x;
    const int lane = tid & 31;
    const int warp = tid >> 5;            // 4 M-warps x 2 N-warps
    const int wm  = (warp >> 1) * 16;
    const int wn8 = (warp & 1) * 8;
    const int r  = lane >> 2;
    const int c2 = (lane & 3) * 2;
    const int bn = blockIdx.x * 16;

    float acc[3][4];
    #pragma unroll
    for (int g = 0; g < 3; g++)
        #pragma unroll
        for (int x = 0; x < 4; x++) acc[g][x] = 0.0f;

    const int arow = tid >> 2, ac8 = (tid & 3) * 8;

    auto load_stage = [&](int s, int k0) {
        CPASYNC16((unsigned)__cvta_generic_to_shared(&sA[s][arow][ac8]),
                  &A[(size_t)arow * HDIM + k0 + ac8]);
        if (tid < 192) {                   // 3 gates x 16 rows x 4 chunks
            int gg  = tid >> 6;            // 0..2
            int rr2 = (tid >> 2) & 15;     // 0..15
            int c8  = (tid & 3) * 8;
            CPASYNC16((unsigned)__cvta_generic_to_shared(&sW[s][gg][rr2][c8]),
                      &W[(size_t)(gg * HDIM + bn + rr2) * HDIM + k0 + c8]);
        }
        CPCOMMIT();
    };

    load_stage(0, 0);
    load_stage(1, 32);
    for (int it = 0; it < 32; it++) {
        if (it + 2 < 32)      { load_stage((it + 2) % 3, (it + 2) * 32); CPWAIT(2); }
        else if (it + 1 < 32) { CPWAIT(1); }
        else                  { CPWAIT(0); }
        __syncthreads();
        const int s = it % 3;
        #pragma unroll
        for (int ks = 0; ks < 2; ks++) {
            unsigned a[4];
            a[0] = *reinterpret_cast<const unsigned*>(&sA[s][wm + r    ][ks * 16 + c2    ]);
            a[1] = *reinterpret_cast<const unsigned*>(&sA[s][wm + r + 8][ks * 16 + c2    ]);
            a[2] = *reinterpret_cast<const unsigned*>(&sA[s][wm + r    ][ks * 16 + c2 + 8]);
            a[3] = *reinterpret_cast<const unsigned*>(&sA[s][wm + r + 8][ks * 16 + c2 + 8]);
            #pragma unroll
            for (int g = 0; g < 3; g++) {
                unsigned b[2];
                int nr = wn8 + r;
                b[0] = *reinterpret_cast<const unsigned*>(&sW[s][g][nr][ks * 16 + c2    ]);
                b[1] = *reinterpret_cast<const unsigned*>(&sW[s][g][nr][ks * 16 + c2 + 8]);
                mma16816(acc[g], a, b);
            }
        }
        __syncthreads();
    }

    // in-register GRU gate on the 4 (row,col) positions this thread owns
    #pragma unroll
    for (int half = 0; half < 2; half++) {
        int row = wm + half * 8 + r;            // b index (0..63)
        #pragma unroll
        for (int e = 0; e < 2; e++) {
            int col = bn + wn8 + c2 + e;        // j index (0..1023)
            float gr = acc[0][half * 2 + e];
            float gz = acc[1][half * 2 + e];
            float gn = acc[2][half * 2 + e];
            if (bias) {
                gr += bias[col];
                gz += bias[HDIM + col];
                gn += bias[2 * HDIM + col];
            }
            if (Xgt) {
                const float* xr = &Xgt[(size_t)row * G3H + col];
                gr += xr[0];
                gz += xr[HDIM];
                gn += xr[2 * HDIM];
            }
            const float* ghp = &GH[(size_t)row * ldgh + col];
            float rr = fast_sigmoid(gr + ghp[0]);
            float zz = fast_sigmoid(gz + ghp[HDIM]);
            float nn = fast_tanh(gn + rr * ghp[2 * HDIM]);
            int hi = row * HDIM + col;
            float hn = (1.0f - zz) * nn + zz * h[hi];
            h[hi]  = hn;
            bf16 hv = __float2bfloat16(hn);
            hb[hi] = hv;
            if (ys) ys[hi] = hv;
        }
    }
}

// ---------------- fused prologue: ALL conversions + gather + bcat + hinit ----------------
__device__ __forceinline__ void cvt4(const float* __restrict__ src, bf16* __restrict__ dst,
                                     size_t j)
{
    float4 f = reinterpret_cast<const float4*>(src)[j];
    __nv_bfloat162* d = reinterpret_cast<__nv_bfloat162*>(dst + j * 4);
    d[0] = __floats2bfloat162_rn(f.x, f.y);
    d[1] = __floats2bfloat162_rn(f.z, f.w);
}
__device__ __forceinline__ void cvt4_str(const float* __restrict__ src, int srcld, int srcoff,
                                         bf16* __restrict__ dst, size_t j)
{
    int cpr = HDIM / 4;
    int r = (int)(j / cpr);
    int c4 = (int)(j % cpr);
    float4 f = *reinterpret_cast<const float4*>(&src[(size_t)r * srcld + srcoff + c4 * 4]);
    __nv_bfloat162* d = reinterpret_cast<__nv_bfloat162*>(dst + (size_t)r * HDIM + c4 * 4);
    d[0] = __floats2bfloat162_rn(f.x, f.y);
    d[1] = __floats2bfloat162_rn(f.z, f.w);
}

#define N_ENCY4 ((size_t)BDIM * SDIM * HDIM / 4)   // 2,097,152
#define N_WK4   ((size_t)HDIM * HDIM / 4)          //   262,144
#define N_WOUT4 ((size_t)VDIM * HDIM / 4)          // 8,192,000
#define N_W3H4  ((size_t)G3H * HDIM / 4)           //   786,432
#define N_WCAT4 ((size_t)QGH * HDIM / 4)           // 1,048,576
#define N_GATH4 ((size_t)TDIM * BDIM * EDIM / 4)   // 1,048,576
#define N_BCAT4 ((size_t)QGH / 4)                  //     1,024
#define N_HIN4  ((size_t)2 * BDIM * HDIM / 4)      //    32,768
#define N_CONV_TOTAL (N_ENCY4 + N_WK4 + N_WOUT4 + 4 * N_W3H4 + N_WCAT4 \
                      + N_GATH4 + N_BCAT4 + N_HIN4)   // 15,827,968 = 61,828 * 256

__global__ __launch_bounds__(256)
void convert_all_kernel(const float* __restrict__ encY, const float* __restrict__ Wk,
                        const float* __restrict__ Wout, const float* __restrict__ Whh0,
                        const float* __restrict__ Wih1, const float* __restrict__ Wih0,
                        const float* __restrict__ Wq,   const float* __restrict__ Whh1,
                        const int* __restrict__ X,      const float* __restrict__ table,
                        const float* __restrict__ bq,   const float* __restrict__ bhh1,
                        const float* __restrict__ h0in)
{
    size_t i = (size_t)blockIdx.x * 256 + threadIdx.x;
    size_t base = 0;
    if (i < base + N_ENCY4) { cvt4(encY, g_encYb, i - base); return; }
    base += N_ENCY4;
    if (i < base + N_WK4)   { cvt4(Wk, g_Wkb, i - base); return; }
    base += N_WK4;
    if (i < base + N_WOUT4) { cvt4(Wout, g_Woutb, i - base); return; }
    base += N_WOUT4;
    if (i < base + N_W3H4)  { cvt4(Whh0, g_Whh0b, i - base); return; }
    base += N_W3H4;
    if (i < base + N_W3H4)  { cvt4(Wih1, g_Wih1b, i - base); return; }
    base += N_W3H4;
    if (i < base + N_W3H4)  { cvt4_str(Wih0, 2 * HDIM, HDIM, g_Wihxb, i - base); return; }
    base += N_W3H4;
    if (i < base + N_W3H4)  { cvt4_str(Wih0, 2 * HDIM, 0, g_Wih0cb, i - base); return; }
    base += N_W3H4;
    if (i < base + N_WCAT4) {
        size_t j = i - base;               // Wcat: [Wq; Whh1]
        size_t e = j * 4;
        int rr = (int)(e / HDIM);
        int c  = (int)(e % HDIM);
        const float* s = (rr < HDIM) ? &Wq[(size_t)rr * HDIM + c]
                                     : &Whh1[(size_t)(rr - HDIM) * HDIM + c];
        float4 f = *reinterpret_cast<const float4*>(s);
        __nv_bfloat162* d = reinterpret_cast<__nv_bfloat162*>(&g_Wcatb[e]);
        d[0] = __floats2bfloat162_rn(f.x, f.y);
        d[1] = __floats2bfloat162_rn(f.z, f.w);
        return;
    }
    base += N_WCAT4;
    if (i < base + N_GATH4) {              // embedding gather -> bf16 (row = t*64+b)
        size_t j = i - base;
        int cpr = EDIM / 4;
        int tb = (int)(j / cpr);
        int c4 = (int)(j % cpr);
        int b = tb & (BDIM - 1);
        int t = tb >> 6;
        float4 f = *reinterpret_cast<const float4*>(
            &table[(size_t)X[b * TDIM + t] * EDIM + c4 * 4]);
        __nv_bfloat162* d = reinterpret_cast<__nv_bfloat162*>(
            &g_xsb[(size_t)tb * EDIM + c4 * 4]);
        d[0] = __floats2bfloat162_rn(f.x, f.y);
        d[1] = __floats2bfloat162_rn(f.z, f.w);
        return;
    }
    base += N_GATH4;
    if (i < base + N_BCAT4) {              // bcat (H divides evenly into vec4 halves)
        size_t j = i - base;
        size_t e = j * 4;
        const float* s = (e < HDIM) ? &bq[e] : &bhh1[e - HDIM];
        *reinterpret_cast<float4*>(&g_bcat[e]) = *reinterpret_cast<const float4*>(s);
        return;
    }
    base += N_BCAT4;
    {                                      // hinit: fp32 copy + bf16 mirror
        size_t j = i - base;
        float4 f = reinterpret_cast<const float4*>(h0in)[j];
        reinterpret_cast<float4*>(g_h)[j] = f;
        __nv_bfloat162* d = reinterpret_cast<__nv_bfloat162*>(&g_hb[j * 4]);
        d[0] = __floats2bfloat162_rn(f.x, f.y);
        d[1] = __floats2bfloat162_rn(f.z, f.w);
    }
}

// ---------------- in-place log-softmax over V (3-pass, champion version) ----------------
__global__ __launch_bounds__(256)
void logsoftmax_kernel(float* __restrict__ out)
{
    float4* p4 = reinterpret_cast<float4*>(out + (size_t)blockIdx.x * VDIM);
    const int n4 = VDIM / 4;
    const int tid = threadIdx.x;

    float m = -1e30f;
    for (int v = tid; v < n4; v += 256) {
        float4 f = p4[v];
        m = fmaxf(m, fmaxf(fmaxf(f.x, f.y), fmaxf(f.z, f.w)));
    }
    m = warpReduceMax(m);
    __shared__ float shm[8];
    if ((tid & 31) == 0) shm[tid >> 5] = m;
    __syncthreads();
    m = shm[0];
    #pragma unroll
    for (int w = 1; w < 8; w++) m = fmaxf(m, shm[w]);

    float s = 0.0f;
    for (int v = tid; v < n4; v += 256) {
        float4 f = p4[v];
        s += __expf(f.x - m) + __expf(f.y - m) + __expf(f.z - m) + __expf(f.w - m);
    }
    s = warpReduceSum(s);
    __shared__ float shs[8];
    if ((tid & 31) == 0) shs[tid >> 5] = s;
    __syncthreads();
    s = shs[0];
    #pragma unroll
    for (int w = 1; w < 8; w++) s += shs[w];

    const float lse = m + logf(s);
    for (int v = tid; v < n4; v += 256) {
        float4 f = p4[v];
        f.x -= lse; f.y -= lse; f.z -= lse; f.w -= lse;
        p4[v] = f;
    }
}

// ---------------- launcher ----------------
extern "C" void kernel_launch(void* const* d_in, const int* in_sizes, int n_in,
                              void* d_out, int out_size)
{
    (void)in_sizes; (void)n_in; (void)out_size;

    const int*   X     = (const int*)d_in[0];
    const float* encY  = (const float*)d_in[1];
    const float* h0in  = (const float*)d_in[2];
    const float* table = (const float*)d_in[3];
    const float* Wq    = (const float*)d_in[4];
    const float* bq    = (const float*)d_in[5];
    const float* Wk    = (const float*)d_in[6];
    const float* bk    = (const float*)d_in[7];
    const float* wv    = (const float*)d_in[8];
    const float* bv    = (const float*)d_in[9];
    const float* Wih0  = (const float*)d_in[10];
    const float* Whh0  = (const float*)d_in[11];
    const float* bih0  = (const float*)d_in[12];
    const float* bhh0  = (const float*)d_in[13];
    const float* Wih1  = (const float*)d_in[14];
    const float* Whh1  = (const float*)d_in[15];
    const float* bih1  = (const float*)d_in[16];
    const float* bhh1  = (const float*)d_in[17];
    const float* Wout  = (const float*)d_in[18];
    const float* bout  = (const float*)d_in[19];
    float* out = (float*)d_out;

    bf16 *kprojb, *encYb, *xsb, *Wihxb, *Wih0cb, *Wih1b, *Woutb, *Wkb, *ysb, *hb, *ctxb;
    float *Xg, *h, *gh0, *qgh1;
    cudaGetSymbolAddress((void**)&kprojb, g_kprojb);
    cudaGetSymbolAddress((void**)&encYb,  g_encYb);
    cudaGetSymbolAddress((void**)&xsb,    g_xsb);
    cudaGetSymbolAddress((void**)&Wihxb,  g_Wihxb);
    cudaGetSymbolAddress((void**)&Wih0cb, g_Wih0cb);
    cudaGetSymbolAddress((void**)&Wih1b,  g_Wih1b);
    cudaGetSymbolAddress((void**)&Woutb,  g_Woutb);
    cudaGetSymbolAddress((void**)&Wkb,    g_Wkb);
    cudaGetSymbolAddress((void**)&ysb,    g_ysb);
    cudaGetSymbolAddress((void**)&hb,     g_hb);
    cudaGetSymbolAddress((void**)&ctxb,   g_ctxb);
    cudaGetSymbolAddress((void**)&Xg,     g_Xg);
    cudaGetSymbolAddress((void**)&h,      g_h);
    cudaGetSymbolAddress((void**)&gh0,    g_gh0);
    cudaGetSymbolAddress((void**)&qgh1,   g_qgh1);

    // ---- prologue: ONE fused conversion/init kernel ----
    convert_all_kernel<<<(unsigned)(N_CONV_TOTAL / 256), 256>>>(
        encY, Wk, Wout, Whh0, Wih1, Wih0, Wq, Whh1, X, table, bq, bhh1, h0in);

    // kproj (bf16 out), Xg (fp32, bih0 folded)
    mma_gemm<bf16, false><<<dim3(HDIM / 128, (BDIM * SDIM) / 128), 256>>>(
        encYb, Wkb, bk, kprojb, BDIM * SDIM, HDIM, HDIM);
    mma_gemm<float, false><<<dim3(G3H / 128, (TDIM * BDIM) / 128), 256>>>(
        xsb, Wihxb, bih0, Xg, TDIM * BDIM, G3H, HDIM);

    bf16* h0b = hb;
    bf16* h1b = hb + BDIM * HDIM;
    float* h0p = h;
    float* h1p = h + BDIM * HDIM;

    // ---- recurrent scan: 5 launches per step ----
    for (int t = 0; t < TDIM; t++) {
        step_start_kernel<<<112, 256>>>(bhh0);
        attn_scores_kernel<<<dim3(SDIM / 4, BDIM), 128>>>(wv, bv);
        ctx_softmax_kernel<<<dim3(4, BDIM), 256>>>();
        gru_fused_kernel<<<64, 256>>>(ctxb, Wih0cb, nullptr,
                                      Xg + (size_t)t * BDIM * G3H,
                                      gh0, G3H, h0p, h0b, nullptr);
        gru_fused_kernel<<<64, 256>>>(h0b, Wih1b, bih1, nullptr,
                                      qgh1 + HDIM, QGH, h1p, h1b,
                                      ysb + (size_t)t * BDIM * HDIM);
    }

    // ---- logits (tensor core, ROWMAP into [B,T,V]) + log-softmax ----
    mma_gemm<float, true><<<dim3(VDIM / 128, (TDIM * BDIM) / 128), 256>>>(
        ysb, Woutb, bout, out, TDIM * BDIM, VDIM, HDIM);
    logsoftmax_kernel<<<BDIM * TDIM, 256>>>(out);
}

// round 17
// speedup vs baseline: 1.1510x; 1.1336x over previous
#include <cuda_runtime.h>
#include <cuda_bf16.h>
#include <cuda_fp16.h>
#include <cstdint>
#include <math.h>

// Problem constants
#define BDIM 64
#define TDIM 64
#define SDIM 128
#define HDIM 1024
#define EDIM 1024
#define VDIM 32000
#define G3H  3072          // 3*H
#define QGH  4096          // q(1024) | gh1(3072)
#define PADH 1032          // padded row length (bf16) for bulk-copy GEMM operands
#define AROWB (PADH * 2)   // 2064 bytes per padded row
#define A_BYTES (64 * AROWB)      // 132096
#define Q_BYTES (16 * AROWB)      // 33024 (16-row W group)

typedef __nv_bfloat16 bf16;

// ---------------- scratch (static device globals; no allocation) ----------------
__device__ bf16  g_kprojb[(size_t)BDIM * SDIM * HDIM];   // [B,S,H] bf16
__device__ bf16  g_encYb [(size_t)BDIM * SDIM * HDIM];
__device__ bf16  g_xsb   [(size_t)TDIM * BDIM * EDIM];   // [T*B, E]
__device__ bf16  g_Wihxb [G3H * HDIM];                   // Wih0[:, H:2H] (mma_gemm, unpadded)
__device__ bf16  g_Wkb   [HDIM * HDIM];
__device__ bf16  g_Woutb [(size_t)VDIM * HDIM];
// padded (bulk-copy) operands
__device__ bf16  g_Wcatp [(size_t)QGH * PADH];           // [Wq; Whh1]
__device__ bf16  g_Whh0p [(size_t)G3H * PADH];
__device__ bf16  g_Wih0cp[(size_t)G3H * PADH];           // Wih0[:, 0:H]
__device__ bf16  g_Wih1p [(size_t)G3H * PADH];
__device__ bf16  g_hbp   [2 * BDIM * PADH];              // bf16 hidden mirror, padded rows
__device__ bf16  g_ctxp  [BDIM * PADH];
__device__ bf16  g_ysb   [(size_t)TDIM * BDIM * HDIM];
__device__ float g_Xg    [(size_t)TDIM * BDIM * G3H];    // x-part of gi0 (+bih0)
__device__ float g_bcat  [QGH];
__device__ float g_h     [2 * BDIM * HDIM];              // fp32 hidden
__device__ float g_qgh1  [BDIM * QGH];                   // per-row: q | gh1
__device__ float g_attn  [BDIM * SDIM];
__device__ float g_gh0   [BDIM * G3H];

// ---------------- helpers ----------------
__device__ __forceinline__ float fast_tanh(float x) {
    float y; asm("tanh.approx.f32 %0, %1;" : "=f"(y) : "f"(x)); return y;
}
__device__ __forceinline__ float fast_sigmoid(float x) {
    return 1.0f / (1.0f + __expf(-x));
}
__device__ __forceinline__ float warpReduceSum(float v) {
    #pragma unroll
    for (int o = 16; o > 0; o >>= 1) v += __shfl_xor_sync(0xffffffffu, v, o);
    return v;
}
__device__ __forceinline__ float warpReduceMax(float v) {
    #pragma unroll
    for (int o = 16; o > 0; o >>= 1) v = fmaxf(v, __shfl_xor_sync(0xffffffffu, v, o));
    return v;
}

__device__ __forceinline__ void mma16816(float* d, const unsigned* a, const unsigned* b) {
    asm volatile(
        "mma.sync.aligned.m16n8k16.row.col.f32.bf16.bf16.f32 "
        "{%0,%1,%2,%3},{%4,%5,%6,%7},{%8,%9},{%0,%1,%2,%3};"
        : "+f"(d[0]), "+f"(d[1]), "+f"(d[2]), "+f"(d[3])
        : "r"(a[0]), "r"(a[1]), "r"(a[2]), "r"(a[3]), "r"(b[0]), "r"(b[1]));
}

#define CPASYNC16(dst_u32, src_ptr) \
    asm volatile("cp.async.cg.shared.global [%0], [%1], 16;" :: "r"(dst_u32), "l"(src_ptr))
#define CPCOMMIT() asm volatile("cp.async.commit_group;")
#define CPWAIT(n)  asm volatile("cp.async.wait_group %0;" :: "n"(n))

#define LDSM_X4(r0, r1, r2, r3, addr) \
    asm volatile("ldmatrix.sync.aligned.m8n8.x4.shared.b16 {%0,%1,%2,%3}, [%4];" \
                 : "=r"(r0), "=r"(r1), "=r"(r2), "=r"(r3) : "r"(addr))
#define LDSM_X2(r0, r1, addr) \
    asm volatile("ldmatrix.sync.aligned.m8n8.x2.shared.b16 {%0,%1}, [%2];" \
                 : "=r"(r0), "=r"(r1) : "r"(addr))

// bulk copy (UBLKCP) + mbarrier
#define CPBULK(dst_u32, src_ptr, nbytes, mbar_u32) \
    asm volatile("cp.async.bulk.shared::cluster.global.mbarrier::complete_tx::bytes " \
                 "[%0], [%1], %2, [%3];" \
                 :: "r"(dst_u32), "l"(src_ptr), "r"(nbytes), "r"(mbar_u32) : "memory")
#define MBAR_INIT(addr, cnt) \
    asm volatile("mbarrier.init.shared.b64 [%0], %1;" :: "r"(addr), "r"(cnt) : "memory")
#define MBAR_EXPECT_TX(addr, bytes) \
    asm volatile("mbarrier.arrive.expect_tx.shared.b64 _, [%0], %1;" \
                 :: "r"(addr), "r"(bytes) : "memory")
#define MBAR_WAIT(addr, par) \
    asm volatile("{\n\t.reg .pred P;\n\tMW_%=:\n\t" \
                 "mbarrier.try_wait.parity.acquire.cta.shared::cta.b64 P, [%0], %1;\n\t" \
                 "@!P bra MW_%=;\n\t}" :: "r"(addr), "r"(par) : "memory")

template <typename T> __device__ __forceinline__ T toOut(float v);
template <> __device__ __forceinline__ float toOut<float>(float v) { return v; }
template <> __device__ __forceinline__ bf16  toOut<bf16 >(float v) { return __float2bfloat16(v); }

// ============ big bf16 tensor-core GEMM (2-stage cp.async + ldmatrix; unpadded ops) ============
template <typename OutT, bool ROWMAP>
__global__ __launch_bounds__(256)
void mma_gemm(const bf16* __restrict__ A, const bf16* __restrict__ B,
              const float* __restrict__ bias, OutT* __restrict__ C,
              int M, int N, int K)
{
    constexpr int BM = 128, BN = 128, BK = 32, PAD = 8;
    __shared__ __align__(16) bf16 As[2][BM][BK + PAD];
    __shared__ __align__(16) bf16 Bs[2][BN][BK + PAD];

    const int bm = blockIdx.y * BM;
    const int bn = blockIdx.x * BN;
    const int tid = threadIdx.x;
    const int lane = tid & 31;
    const int warp = tid >> 5;
    const int wm = (warp >> 2) * 64;
    const int wn = (warp & 3) * 32;

    float acc[4][4][4];
    #pragma unroll
    for (int i = 0; i < 4; i++)
        #pragma unroll
        for (int j = 0; j < 4; j++)
            #pragma unroll
            for (int x = 0; x < 4; x++) acc[i][j][x] = 0.0f;

    const int r  = lane >> 2;
    const int c2 = (lane & 3) * 2;
    const int lrowA = lane & 15;
    const int lkA   = (lane >> 4) * 8;
    const int lrowB = lane & 7;
    const int gB    = lane >> 3;

    auto load_stage = [&](int s, int k0) {
        #pragma unroll
        for (int v = 0; v < 2; v++) {
            int idx = tid + v * 256;
            int row = idx >> 2;
            int c8  = (idx & 3) * 8;
            CPASYNC16((unsigned)__cvta_generic_to_shared(&As[s][row][c8]),
                      &A[(size_t)(bm + row) * K + k0 + c8]);
            CPASYNC16((unsigned)__cvta_generic_to_shared(&Bs[s][row][c8]),
                      &B[(size_t)(bn + row) * K + k0 + c8]);
        }
        CPCOMMIT();
    };

    const int NIT = K / BK;
    load_stage(0, 0);

    for (int it = 0; it < NIT; it++) {
        if (it + 1 < NIT) load_stage((it + 1) & 1, (it + 1) * BK);
        if (it + 1 < NIT) { CPWAIT(1); } else { CPWAIT(0); }
        __syncthreads();
        const int s = it & 1;

        #pragma unroll
        for (int ks = 0; ks < 2; ks++) {
            unsigned a[4][4], b[4][2];
            #pragma unroll
            for (int i = 0; i < 4; i++) {
                unsigned ad = (unsigned)__cvta_generic_to_shared(
                    &As[s][wm + i * 16 + lrowA][ks * 16 + lkA]);
                LDSM_X4(a[i][0], a[i][1], a[i][2], a[i][3], ad);
            }
            #pragma unroll
            for (int jj = 0; jj < 2; jj++) {
                unsigned bd = (unsigned)__cvta_generic_to_shared(
                    &Bs[s][wn + (jj * 2 + (gB >> 1)) * 8 + lrowB][ks * 16 + (gB & 1) * 8]);
                unsigned r0, r1, r2, r3;
                LDSM_X4(r0, r1, r2, r3, bd);
                b[jj * 2][0] = r0; b[jj * 2][1] = r1;
                b[jj * 2 + 1][0] = r2; b[jj * 2 + 1][1] = r3;
            }
            #pragma unroll
            for (int i = 0; i < 4; i++)
                #pragma unroll
                for (int j = 0; j < 4; j++)
                    mma16816(acc[i][j], a[i], b[j]);
        }
        __syncthreads();
    }

    #pragma unroll
    for (int i = 0; i < 4; i++) {
        int grow0 = bm + wm + i * 16 + r;
        #pragma unroll
        for (int half = 0; half < 2; half++) {
            int g = grow0 + half * 8;
            size_t rowBase;
            if (ROWMAP) {
                int b_ = g & (BDIM - 1);
                int t_ = g >> 6;
                rowBase = (size_t)(b_ * TDIM + t_) * N;
            } else {
                rowBase = (size_t)g * N;
            }
            #pragma unroll
            for (int j = 0; j < 4; j++) {
                int col = bn + wn + j * 8 + c2;
                float b0 = bias ? bias[col]     : 0.0f;
                float b1 = bias ? bias[col + 1] : 0.0f;
                C[rowBase + col    ] = toOut<OutT>(acc[i][j][half * 2    ] + b0);
                C[rowBase + col + 1] = toOut<OutT>(acc[i][j][half * 2 + 1] + b1);
            }
        }
    }
}

// ============ step-start: bulk-copy GEMM. 112 blocks; blk<64: qgh1=h1@Wcat^T+bcat; else gh0 ============
// smem: A[64][1032] (132096 B) + 2 W quarter buffers (33024 B each) = 198144 B dynamic
__global__ __launch_bounds__(256)
void step_start_kernel(const float* __restrict__ bhh0)
{
    extern __shared__ __align__(128) char smem[];
    __shared__ __align__(8) unsigned long long s_mbar[4];

    const int tid = threadIdx.x;
    const int lane = tid & 31;
    const int warp = tid >> 5;
    const bool isQ = blockIdx.x < 64;
    const int bn = (isQ ? blockIdx.x : blockIdx.x - 64) * 64;
    const bf16* Ag = g_hbp + (isQ ? BDIM * PADH : 0);   // h1 for Wcat, h0 for Whh0
    const bf16* Wg = isQ ? g_Wcatp : g_Whh0p;
    float* Cout = isQ ? g_qgh1 : g_gh0;
    const int ldc = isQ ? QGH : G3H;
    const float* bias = isQ ? g_bcat : bhh0;

    const unsigned sA = (unsigned)__cvta_generic_to_shared(smem);
    const unsigned sW0 = sA + A_BYTES;
    const unsigned mb0 = (unsigned)__cvta_generic_to_shared(&s_mbar[0]);

    if (tid == 0) {
        #pragma unroll
        for (int i = 0; i < 4; i++) MBAR_INIT(mb0 + i * 8, 1u);
    }
    __syncthreads();
    if (tid == 0) {
        MBAR_EXPECT_TX(mb0, (unsigned)(A_BYTES + Q_BYTES));
        CPBULK(sA, Ag, (unsigned)A_BYTES, mb0);
        CPBULK(sW0, Wg + (size_t)bn * PADH, (unsigned)Q_BYTES, mb0);
        MBAR_EXPECT_TX(mb0 + 8, (unsigned)Q_BYTES);
        CPBULK(sW0 + Q_BYTES, Wg + (size_t)(bn + 16) * PADH, (unsigned)Q_BYTES, mb0 + 8);
    }

    const int wm  = (warp >> 1) * 16;      // 4 M-warps x 2 N-warps
    const int wn8 = (warp & 1) * 8;
    const int r  = lane >> 2;
    const int c2 = (lane & 3) * 2;

    const unsigned aAddr = sA + (unsigned)(wm + (lane & 15)) * AROWB
                              + (unsigned)((lane >> 4) * 8) * 2;
    const int bl = lane & 15;
    const unsigned bOff = (unsigned)(wn8 + (bl & 7)) * AROWB
                        + (unsigned)(((bl >> 3) & 1) * 8) * 2;

    for (int q = 0; q < 4; q++) {
        MBAR_WAIT(mb0 + q * 8, 0u);
        const unsigned wbase = sW0 + (unsigned)(q & 1) * Q_BYTES + bOff;
        float acc0[4] = {0.f, 0.f, 0.f, 0.f};
        float acc1[4] = {0.f, 0.f, 0.f, 0.f};
        #pragma unroll 4
        for (int kk = 0; kk < 64; kk += 2) {
            unsigned a0[4], b0[2], a1[4], b1[2];
            LDSM_X4(a0[0], a0[1], a0[2], a0[3], aAddr + kk * 32);
            LDSM_X2(b0[0], b0[1], wbase + kk * 32);
            mma16816(acc0, a0, b0);
            LDSM_X4(a1[0], a1[1], a1[2], a1[3], aAddr + kk * 32 + 32);
            LDSM_X2(b1[0], b1[1], wbase + kk * 32 + 32);
            mma16816(acc1, a1, b1);
        }
        const int colbase = bn + q * 16 + wn8 + c2;
        #pragma unroll
        for (int half = 0; half < 2; half++) {
            int row = wm + half * 8 + r;
            float v0 = acc0[half * 2]     + acc1[half * 2]     + bias[colbase];
            float v1 = acc0[half * 2 + 1] + acc1[half * 2 + 1] + bias[colbase + 1];
            Cout[(size_t)row * ldc + colbase]     = v0;
            Cout[(size_t)row * ldc + colbase + 1] = v1;
        }
        __syncthreads();
        if (tid == 0 && q + 2 < 4) {
            MBAR_EXPECT_TX(mb0 + (q + 2) * 8, (unsigned)Q_BYTES);
            CPBULK(sW0 + (unsigned)(q & 1) * Q_BYTES,
                   Wg + (size_t)(bn + (q + 2) * 16) * PADH, (unsigned)Q_BYTES,
                   mb0 + (q + 2) * 8);
        }
    }
}
#define SS_SMEM (A_BYTES + 2 * Q_BYTES)    // 198144

// ============ fused GRU: bulk-copy gi GEMM (16 cols x 3 gates, 64 blocks) + in-register gate ======
// smem: A 132096 + 3 gate slabs (33024 each) = 231168 B dynamic
__global__ __launch_bounds__(256)
void gru_fused_kernel(const bf16* __restrict__ Ag, const bf16* __restrict__ Wg,
                      const float* __restrict__ bias, const float* __restrict__ Xgt,
                      const float* __restrict__ GH, int ldgh,
                      float* __restrict__ h, bf16* __restrict__ hbp,
                      bf16* __restrict__ ys)
{
    extern __shared__ __align__(128) char smem[];
    __shared__ __align__(8) unsigned long long s_mbar;

    const int tid = threadIdx.x;
    const int lane = tid & 31;
    const int warp = tid >> 5;
    const int bn = blockIdx.x * 16;

    const unsigned sA = (unsigned)__cvta_generic_to_shared(smem);
    const unsigned mb = (unsigned)__cvta_generic_to_shared(&s_mbar);

    if (tid == 0) MBAR_INIT(mb, 1u);
    __syncthreads();
    if (tid == 0) {
        MBAR_EXPECT_TX(mb, (unsigned)(A_BYTES + 3 * Q_BYTES));
        CPBULK(sA, Ag, (unsigned)A_BYTES, mb);
        #pragma unroll
        for (int g = 0; g < 3; g++)
            CPBULK(sA + A_BYTES + g * Q_BYTES,
                   Wg + (size_t)(g * HDIM + bn) * PADH, (unsigned)Q_BYTES, mb);
    }

    const int wm  = (warp >> 1) * 16;      // 4 M-warps x 2 N-warps
    const int wn8 = (warp & 1) * 8;
    const int r  = lane >> 2;
    const int c2 = (lane & 3) * 2;

    const unsigned aAddr = sA + (unsigned)(wm + (lane & 15)) * AROWB
                              + (unsigned)((lane >> 4) * 8) * 2;
    const int bl = lane & 15;
    const unsigned bOff = (unsigned)(wn8 + (bl & 7)) * AROWB
                        + (unsigned)(((bl >> 3) & 1) * 8) * 2;
    const unsigned wb0 = sA + A_BYTES + bOff;

    MBAR_WAIT(mb, 0u);

    float acc[3][4];
    #pragma unroll
    for (int g = 0; g < 3; g++)
        #pragma unroll
        for (int x = 0; x < 4; x++) acc[g][x] = 0.0f;

    #pragma unroll 4
    for (int kk = 0; kk < 64; kk++) {
        unsigned a[4];
        LDSM_X4(a[0], a[1], a[2], a[3], aAddr + kk * 32);
        #pragma unroll
        for (int g = 0; g < 3; g++) {
            unsigned b[2];
            LDSM_X2(b[0], b[1], wb0 + (unsigned)g * Q_BYTES + kk * 32);
            mma16816(acc[g], a, b);
        }
    }

    // in-register GRU gate on the 4 (row,col) positions this thread owns
    #pragma unroll
    for (int half = 0; half < 2; half++) {
        int row = wm + half * 8 + r;            // b index (0..63)
        #pragma unroll
        for (int e = 0; e < 2; e++) {
            int col = bn + wn8 + c2 + e;        // j index (0..1023)
            float gr = acc[0][half * 2 + e];
            float gz = acc[1][half * 2 + e];
            float gn = acc[2][half * 2 + e];
            if (bias) {
                gr += bias[col];
                gz += bias[HDIM + col];
                gn += bias[2 * HDIM + col];
            }
            if (Xgt) {
                const float* xr = &Xgt[(size_t)row * G3H + col];
                gr += xr[0];
                gz += xr[HDIM];
                gn += xr[2 * HDIM];
            }
            const float* ghp = &GH[(size_t)row * ldgh + col];
            float rr = fast_sigmoid(gr + ghp[0]);
            float zz = fast_sigmoid(gz + ghp[HDIM]);
            float nn = fast_tanh(gn + rr * ghp[2 * HDIM]);
            int hi = row * HDIM + col;
            float hn = (1.0f - zz) * nn + zz * h[hi];
            h[hi] = hn;
            bf16 hv = __float2bfloat16(hn);
            hbp[row * PADH + col] = hv;
            if (ys) ys[hi] = hv;
        }
    }
}
#define GRU_SMEM (A_BYTES + 3 * Q_BYTES)   // 231168

// ---------------- attention scores: grid (32, 64), 128 thr; warp w -> s = blk*4+w ----
__global__ __launch_bounds__(128)
void attn_scores_kernel(const float* __restrict__ wv, const float* __restrict__ bv)
{
    const int lane = threadIdx.x & 31;
    const int warp = threadIdx.x >> 5;
    const int b = blockIdx.y;
    const int s = blockIdx.x * 4 + warp;

    const __nv_bfloat162* kp =
        reinterpret_cast<const __nv_bfloat162*>(&g_kprojb[((size_t)b * SDIM + s) * HDIM]);
    const float2* q2  = reinterpret_cast<const float2*>(&g_qgh1[(size_t)b * QGH]);
    const float2* wv2 = reinterpret_cast<const float2*>(wv);

    float sum = 0.0f;
    #pragma unroll 4
    for (int i = lane; i < HDIM / 2; i += 32) {
        __nv_bfloat162 k = kp[i];
        float2 q = q2[i];
        float2 w = wv2[i];
        __half2 hx = __floats2half2_rn(q.x + __low2float(k), q.y + __high2float(k));
        unsigned hin = *reinterpret_cast<unsigned*>(&hx);
        unsigned hout;
        asm("tanh.approx.f16x2 %0, %1;" : "=r"(hout) : "r"(hin));
        __half2 ht = *reinterpret_cast<__half2*>(&hout);
        float2 tv = __half22float2(ht);
        sum += tv.x * w.x + tv.y * w.y;
    }
    sum = warpReduceSum(sum);
    if (lane == 0) g_attn[b * SDIM + s] = sum + bv[0];
}

// ---------------- fused softmax + context: grid (4, B), 256 thr; ctx -> padded ----------------
__global__ __launch_bounds__(256)
void ctx_softmax_kernel()
{
    const int b = blockIdx.y;
    const int tid = threadIdx.x;
    __shared__ float sc[SDIM];
    __shared__ float red[8];

    float v = (tid < SDIM) ? g_attn[b * SDIM + tid] : -1e30f;
    float m = warpReduceMax(v);
    if ((tid & 31) == 0) red[tid >> 5] = m;
    __syncthreads();
    m = red[0];
    #pragma unroll
    for (int w = 1; w < 8; w++) m = fmaxf(m, red[w]);

    float e = (tid < SDIM) ? __expf(v - m) : 0.0f;
    float s = warpReduceSum(e);
    __syncthreads();
    if ((tid & 31) == 0) red[tid >> 5] = s;
    __syncthreads();
    float tot = red[0];
    #pragma unroll
    for (int w = 1; w < 8; w++) tot += red[w];

    if (tid < SDIM) sc[tid] = e / tot;
    __syncthreads();

    const int h = blockIdx.x * 256 + tid;
    const bf16* ey = &g_encYb[(size_t)b * SDIM * HDIM + h];
    float acc = 0.0f;
    #pragma unroll 8
    for (int s2 = 0; s2 < SDIM; s2++)
        acc = fmaf(sc[s2], __bfloat162float(ey[(size_t)s2 * HDIM]), acc);
    g_ctxp[b * PADH + h] = __float2bfloat16(acc);
}

// ---------------- fused prologue: ALL conversions + gather + bcat + hinit ----------------
__device__ __forceinline__ void cvt4(const float* __restrict__ src, bf16* __restrict__ dst,
                                     size_t j)
{
    float4 f = reinterpret_cast<const float4*>(src)[j];
    __nv_bfloat162* d = reinterpret_cast<__nv_bfloat162*>(dst + j * 4);
    d[0] = __floats2bfloat162_rn(f.x, f.y);
    d[1] = __floats2bfloat162_rn(f.z, f.w);
}
// linear fp32 source -> PADDED bf16 dest (rows of HDIM -> rows of PADH)
__device__ __forceinline__ void cvt4p(const float* __restrict__ src, bf16* __restrict__ dst,
                                      size_t j)
{
    int row = (int)(j >> 8);               // 256 vec4 per 1024-row
    int c4  = (int)(j & 255);
    float4 f = reinterpret_cast<const float4*>(src)[j];
    __nv_bfloat162* d = reinterpret_cast<__nv_bfloat162*>(dst + (size_t)row * PADH + c4 * 4);
    d[0] = __floats2bfloat162_rn(f.x, f.y);
    d[1] = __floats2bfloat162_rn(f.z, f.w);
}
// strided fp32 source (ld srcld, offset srcoff) -> PADDED bf16 dest
__device__ __forceinline__ void cvt4_strp(const float* __restrict__ src, int srcld, int srcoff,
                                          bf16* __restrict__ dst, size_t j)
{
    int row = (int)(j >> 8);
    int c4  = (int)(j & 255);
    float4 f = *reinterpret_cast<const float4*>(&src[(size_t)row * srcld + srcoff + c4 * 4]);
    __nv_bfloat162* d = reinterpret_cast<__nv_bfloat162*>(dst + (size_t)row * PADH + c4 * 4);
    d[0] = __floats2bfloat162_rn(f.x, f.y);
    d[1] = __floats2bfloat162_rn(f.z, f.w);
}

#define N_ENCY4 ((size_t)BDIM * SDIM * HDIM / 4)   // 2,097,152
#define N_WK4   ((size_t)HDIM * HDIM / 4)          //   262,144
#define N_WOUT4 ((size_t)VDIM * HDIM / 4)          // 8,192,000
#define N_W3H4  ((size_t)G3H * HDIM / 4)           //   786,432
#define N_WCAT4 ((size_t)QGH * HDIM / 4)           // 1,048,576
#define N_GATH4 ((size_t)TDIM * BDIM * EDIM / 4)   // 1,048,576
#define N_BCAT4 ((size_t)QGH / 4)                  //     1,024
#define N_HIN4  ((size_t)2 * BDIM * HDIM / 4)      //    32,768
#define N_CONV_TOTAL (N_ENCY4 + N_WK4 + N_WOUT4 + 4 * N_W3H4 + N_WCAT4 \
                      + N_GATH4 + N_BCAT4 + N_HIN4)   // 15,827,968 = 61,828 * 256

__global__ __launch_bounds__(256)
void convert_all_kernel(const float* __restrict__ encY, const float* __restrict__ Wk,
                        const float* __restrict__ Wout, const float* __restrict__ Whh0,
                        const float* __restrict__ Wih1, const float* __restrict__ Wih0,
                        const float* __restrict__ Wq,   const float* __restrict__ Whh1,
                        const int* __restrict__ X,      const float* __restrict__ table,
                        const float* __restrict__ bq,   const float* __restrict__ bhh1,
                        const float* __restrict__ h0in)
{
    size_t i = (size_t)blockIdx.x * 256 + threadIdx.x;
    size_t base = 0;
    if (i < base + N_ENCY4) { cvt4(encY, g_encYb, i - base); return; }
    base += N_ENCY4;
    if (i < base + N_WK4)   { cvt4(Wk, g_Wkb, i - base); return; }
    base += N_WK4;
    if (i < base + N_WOUT4) { cvt4(Wout, g_Woutb, i - base); return; }
    base += N_WOUT4;
    if (i < base + N_W3H4)  { cvt4p(Whh0, g_Whh0p, i - base); return; }
    base += N_W3H4;
    if (i < base + N_W3H4)  { cvt4p(Wih1, g_Wih1p, i - base); return; }
    base += N_W3H4;
    if (i < base + N_W3H4)  { cvt4(Wih0 + HDIM, g_Wihxb, 0), cvt4_strp(Wih0, 2 * HDIM, HDIM, g_Wihxb, i - base); return; }
    base += N_W3H4;
    if (i < base + N_W3H4)  { cvt4_strp(Wih0, 2 * HDIM, 0, g_Wih0cp, i - base); return; }
    base += N_W3H4;
    if (i < base + N_WCAT4) {
        size_t j = i - base;               // Wcat: [Wq; Whh1] -> padded
        int rr = (int)(j >> 8);
        int c4 = (int)(j & 255);
        const float* s = (rr < HDIM) ? &Wq[(size_t)rr * HDIM + c4 * 4]
                                     : &Whh1[(size_t)(rr - HDIM) * HDIM + c4 * 4];
        float4 f = *reinterpret_cast<const float4*>(s);
        __nv_bfloat162* d = reinterpret_cast<__nv_bfloat162*>(
            &g_Wcatp[(size_t)rr * PADH + c4 * 4]);
        d[0] = __floats2bfloat162_rn(f.x, f.y);
        d[1] = __floats2bfloat162_rn(f.z, f.w);
        return;
    }
    base += N_WCAT4;
    if (i < base + N_GATH4) {              // embedding gather -> bf16 (row = t*64+b, unpadded)
        size_t j = i - base;
        int cpr = EDIM / 4;
        int tb = (int)(j / cpr);
        int c4 = (int)(j % cpr);
        int b = tb & (BDIM - 1);
        int t = tb >> 6;
        float4 f = *reinterpret_cast<const float4*>(
            &table[(size_t)X[b * TDIM + t] * EDIM + c4 * 4]);
        __nv_bfloat162* d = reinterpret_cast<__nv_bfloat162*>(
            &g_xsb[(size_t)tb * EDIM + c4 * 4]);
        d[0] = __floats2bfloat162_rn(f.x, f.y);
        d[1] = __floats2bfloat162_rn(f.z, f.w);
        return;
    }
    base += N_GATH4;
    if (i < base + N_BCAT4) {              // bcat
        size_t j = i - base;
        size_t e = j * 4;
        const float* s = (e < HDIM) ? &bq[e] : &bhh1[e - HDIM];
        *reinterpret_cast<float4*>(&g_bcat[e]) = *reinterpret_cast<const float4*>(s);
        return;
    }
    base += N_BCAT4;
    {                                      // hinit: fp32 copy + PADDED bf16 mirror
        size_t j = i - base;
        float4 f = reinterpret_cast<const float4*>(h0in)[j];
        reinterpret_cast<float4*>(g_h)[j] = f;
        int row = (int)(j >> 8);
        int c4  = (int)(j & 255);
        __nv_bfloat162* d = reinterpret_cast<__nv_bfloat162*>(
            &g_hbp[(size_t)row * PADH + c4 * 4]);
        d[0] = __floats2bfloat162_rn(f.x, f.y);
        d[1] = __floats2bfloat162_rn(f.z, f.w);
    }
}

// ---------------- in-place log-softmax over V (3-pass, champion version) ----------------
__global__ __launch_bounds__(256)
void logsoftmax_kernel(float* __restrict__ out)
{
    float4* p4 = reinterpret_cast<float4*>(out + (size_t)blockIdx.x * VDIM);
    const int n4 = VDIM / 4;
    const int tid = threadIdx.x;

    float m = -1e30f;
    for (int v = tid; v < n4; v += 256) {
        float4 f = p4[v];
        m = fmaxf(m, fmaxf(fmaxf(f.x, f.y), fmaxf(f.z, f.w)));
    }
    m = warpReduceMax(m);
    __shared__ float shm[8];
    if ((tid & 31) == 0) shm[tid >> 5] = m;
    __syncthreads();
    m = shm[0];
    #pragma unroll
    for (int w = 1; w < 8; w++) m = fmaxf(m, shm[w]);

    float s = 0.0f;
    for (int v = tid; v < n4; v += 256) {
        float4 f = p4[v];
        s += __expf(f.x - m) + __expf(f.y - m) + __expf(f.z - m) + __expf(f.w - m);
    }
    s = warpReduceSum(s);
    __shared__ float shs[8];
    if ((tid & 31) == 0) shs[tid >> 5] = s;
    __syncthreads();
    s = shs[0];
    #pragma unroll
    for (int w = 1; w < 8; w++) s += shs[w];

    const float lse = m + logf(s);
    for (int v = tid; v < n4; v += 256) {
        float4 f = p4[v];
        f.x -= lse; f.y -= lse; f.z -= lse; f.w -= lse;
        p4[v] = f;
    }
}

// ---------------- launcher ----------------
extern "C" void kernel_launch(void* const* d_in, const int* in_sizes, int n_in,
                              void* d_out, int out_size)
{
    (void)in_sizes; (void)n_in; (void)out_size;

    const int*   X     = (const int*)d_in[0];
    const float* encY  = (const float*)d_in[1];
    const float* h0in  = (const float*)d_in[2];
    const float* table = (const float*)d_in[3];
    const float* Wq    = (const float*)d_in[4];
    const float* bq    = (const float*)d_in[5];
    const float* Wk    = (const float*)d_in[6];
    const float* bk    = (const float*)d_in[7];
    const float* wv    = (const float*)d_in[8];
    const float* bv    = (const float*)d_in[9];
    const float* Wih0  = (const float*)d_in[10];
    const float* Whh0  = (const float*)d_in[11];
    const float* bih0  = (const float*)d_in[12];
    const float* bhh0  = (const float*)d_in[13];
    const float* Wih1  = (const float*)d_in[14];
    const float* Whh1  = (const float*)d_in[15];
    const float* bih1  = (const float*)d_in[16];
    const float* bhh1  = (const float*)d_in[17];
    const float* Wout  = (const float*)d_in[18];
    const float* bout  = (const float*)d_in[19];
    float* out = (float*)d_out;

    bf16 *kprojb, *encYb, *xsb, *Wihxb, *Woutb, *Wkb, *ysb, *hbp, *ctxp, *Wih0cp, *Wih1p;
    float *Xg, *h, *gh0, *qgh1;
    cudaGetSymbolAddress((void**)&kprojb, g_kprojb);
    cudaGetSymbolAddress((void**)&encYb,  g_encYb);
    cudaGetSymbolAddress((void**)&xsb,    g_xsb);
    cudaGetSymbolAddress((void**)&Wihxb,  g_Wihxb);
    cudaGetSymbolAddress((void**)&Woutb,  g_Woutb);
    cudaGetSymbolAddress((void**)&Wkb,    g_Wkb);
    cudaGetSymbolAddress((void**)&ysb,    g_ysb);
    cudaGetSymbolAddress((void**)&hbp,    g_hbp);
    cudaGetSymbolAddress((void**)&ctxp,   g_ctxp);
    cudaGetSymbolAddress((void**)&Wih0cp, g_Wih0cp);
    cudaGetSymbolAddress((void**)&Wih1p,  g_Wih1p);
    cudaGetSymbolAddress((void**)&Xg,     g_Xg);
    cudaGetSymbolAddress((void**)&h,      g_h);
    cudaGetSymbolAddress((void**)&gh0,    g_gh0);
    cudaGetSymbolAddress((void**)&qgh1,   g_qgh1);

    cudaFuncSetAttribute(step_start_kernel,
                         cudaFuncAttributeMaxDynamicSharedMemorySize, SS_SMEM);
    cudaFuncSetAttribute(gru_fused_kernel,
                         cudaFuncAttributeMaxDynamicSharedMemorySize, GRU_SMEM);

    // ---- prologue: ONE fused conversion/init kernel ----
    convert_all_kernel<<<(unsigned)(N_CONV_TOTAL / 256), 256>>>(
        encY, Wk, Wout, Whh0, Wih1, Wih0, Wq, Whh1, X, table, bq, bhh1, h0in);

    // kproj (bf16 out), Xg (fp32, bih0 folded)
    mma_gemm<bf16, false><<<dim3(HDIM / 128, (BDIM * SDIM) / 128), 256>>>(
        encYb, Wkb, bk, kprojb, BDIM * SDIM, HDIM, HDIM);
    mma_gemm<float, false><<<dim3(G3H / 128, (TDIM * BDIM) / 128), 256>>>(
        xsb, Wihxb, bih0, Xg, TDIM * BDIM, G3H, HDIM);

    bf16* h0bp = hbp;
    bf16* h1bp = hbp + BDIM * PADH;
    float* h0p = h;
    float* h1p = h + BDIM * HDIM;

    // ---- recurrent scan: 5 launches per step ----
    for (int t = 0; t < TDIM; t++) {
        step_start_kernel<<<112, 256, SS_SMEM>>>(bhh0);
        attn_scores_kernel<<<dim3(SDIM / 4, BDIM), 128>>>(wv, bv);
        ctx_softmax_kernel<<<dim3(4, BDIM), 256>>>();
        gru_fused_kernel<<<64, 256, GRU_SMEM>>>(ctxp, Wih0cp, nullptr,
                                                Xg + (size_t)t * BDIM * G3H,
                                                gh0, G3H, h0p, h0bp, nullptr);
        gru_fused_kernel<<<64, 256, GRU_SMEM>>>(h0bp, Wih1p, bih1, nullptr,
                                                qgh1 + HDIM, QGH, h1p, h1bp,
                                                ysb + (size_t)t * BDIM * HDIM);
    }

    // ---- logits (tensor core, ROWMAP into [B,T,V]) + log-softmax ----
    mma_gemm<float, true><<<dim3(VDIM / 128, (TDIM * BDIM) / 128), 256>>>(
        ysb, Woutb, bout, out, TDIM * BDIM, VDIM, HDIM);
    logsoftmax_kernel<<<BDIM * TDIM, 256>>>(out);
}